// round 10
// baseline (speedup 1.0000x reference)
#include <cuda_runtime.h>
#include <cuda_bf16.h>
#include <math.h>

#define BB 8
#define IMG 256
#define INCH 2
#define PSZ 16
#define EE 256
#define DEPTH 8
#define HPN 16
#define LL 256
#define DI 512
#define DS 16
#define DTRN 16
#define DCN 4
#define NTOK 2048          // B*L
#define XZW 1024           // 2*DI

// ---------------- scratch ----------------
__device__ float g_temb[BB*EE];
__device__ float g_h[NTOK*EE];
__device__ float g_patches[NTOK*512];
__device__ float g_xz[NTOK*XZW];
__device__ float g_ut[BB*DI*LL];    // u transposed [b][d][t]
__device__ float g_dtt[BB*DI*LL];   // dt transposed [b][d][t]
__device__ float g_zs[BB*DI*LL];    // silu(z) transposed [b][d][t]
__device__ float g_bc[NTOK*32];     // B[16],C[16] per token
__device__ float g_yt[BB*DI*LL];    // y transposed [b][d][t]
__device__ float g_feat[BB*EE*HPN*HPN];
__device__ float g_d1[BB*128*32*32];
__device__ float g_d2[BB*64*64*64];
__device__ float g_d3[BB*32*128*128];
// packed bf16 hi/lo weight buffers (word idx = n*K + k; even word=hi pair, odd=lo pair)
__device__ unsigned g_wp_in[DEPTH*XZW*EE];
__device__ unsigned g_wp_out[DEPTH*EE*DI];
__device__ unsigned g_wp_patch[EE*512];

__device__ __forceinline__ float geluf(float v){ return 0.5f*v*(1.0f+erff(v*0.70710678118654752f)); }
__device__ __forceinline__ float siluf(float v){ return v/(1.0f+__expf(-v)); }

__device__ __forceinline__ void mma16(float* d, const unsigned* a, unsigned b0, unsigned b1){
  asm volatile("mma.sync.aligned.m16n8k16.row.col.f32.bf16.bf16.f32 "
    "{%0,%1,%2,%3}, {%4,%5,%6,%7}, {%8,%9}, {%0,%1,%2,%3};"
    : "+f"(d[0]),"+f"(d[1]),"+f"(d[2]),"+f"(d[3])
    : "r"(a[0]),"r"(a[1]),"r"(a[2]),"r"(a[3]), "r"(b0),"r"(b1));
}

// split float4 (4 consecutive k = 2 kpairs) into interleaved {hi,lo,hi,lo} words; one STS.128
__device__ __forceinline__ void store_split(unsigned* base, int widx, float4 v){
  __nv_bfloat162 h0 = __floats2bfloat162_rn(v.x, v.y);
  __nv_bfloat162 h1 = __floats2bfloat162_rn(v.z, v.w);
  float r0 = v.x - __bfloat162float(h0.x);
  float r1 = v.y - __bfloat162float(h0.y);
  float r2 = v.z - __bfloat162float(h1.x);
  float r3 = v.w - __bfloat162float(h1.y);
  __nv_bfloat162 l0 = __floats2bfloat162_rn(r0, r1);
  __nv_bfloat162 l1 = __floats2bfloat162_rn(r2, r3);
  uint4 w;
  w.x = *(unsigned*)&h0; w.y = *(unsigned*)&l0;
  w.z = *(unsigned*)&h1; w.w = *(unsigned*)&l1;
  *(uint4*)(base + widx) = w;
}
// pack one kpair (a0=k, a1=k+1) -> {hi,lo} uint2 at word widx (even)
__device__ __forceinline__ void store_split2(unsigned* base, int widx, float a0, float a1){
  __nv_bfloat162 h = __floats2bfloat162_rn(a0, a1);
  float r0 = a0 - __bfloat162float(h.x);
  float r1 = a1 - __bfloat162float(h.y);
  __nv_bfloat162 l = __floats2bfloat162_rn(r0, r1);
  uint2 w; w.x = *(unsigned*)&h; w.y = *(unsigned*)&l;
  *(uint2*)(base + widx) = w;
}

// ---------------- weight pre-pack: float [.. ][K] -> packed words ----------------
__global__ void wpack_kernel(const float* __restrict__ W, unsigned* __restrict__ P, int total_pairs){
  int idx = blockIdx.x*blockDim.x + threadIdx.x;
  if (idx >= total_pairs) return;
  float2 v = *(const float2*)(W + (size_t)idx*2);
  __nv_bfloat162 h = __floats2bfloat162_rn(v.x, v.y);
  float r0 = v.x - __bfloat162float(h.x);
  float r1 = v.y - __bfloat162float(h.y);
  __nv_bfloat162 l = __floats2bfloat162_rn(r0, r1);
  uint2 w; w.x = *(unsigned*)&h; w.y = *(unsigned*)&l;
  *(uint2*)(P + (size_t)idx*2) = w;
}

// ---------------- time embedding ----------------
__global__ void time_emb_kernel(const int* __restrict__ t, const float* __restrict__ w1,
                                const float* __restrict__ b1, const float* __restrict__ w2,
                                const float* __restrict__ b2){
  __shared__ float hdn[EE];
  int b = blockIdx.x; int j = threadIdx.x;
  float tf = (float)t[b];
  hdn[j] = geluf(tf*w1[j] + b1[j]);
  __syncthreads();
  float acc = b2[j];
  #pragma unroll 8
  for (int k=0;k<EE;k++) acc = fmaf(hdn[k], w2[k*EE + j], acc);
  g_temb[b*EE + j] = acc;
}

// ---------------- im2col patch gather ----------------
__global__ void patch_gather_kernel(const float* __restrict__ x){
  int idx = blockIdx.x*blockDim.x + threadIdx.x;
  int k = idx & 511; int tok = idx >> 9;
  int l = tok & (LL-1); int b = tok >> 8;
  int c = k >> 8; int rem = k & 255; int p = rem >> 4; int q = rem & 15;
  int hp = l >> 4; int wp = l & 15;
  g_patches[idx] = x[(((size_t)(b*INCH + c))*IMG + hp*PSZ + p)*IMG + wp*PSZ + q];
}

// ================= bf16x3 tensor-core GEMM (interleaved hi/lo, packed weights) ==========
// C[M,N] = A[M,K] @ W[N,K]^T. Block (64*MTILES)x64, BK=32, 8 warps (4m x 2n).
// smem word idx(m,kp,plane) = m*40 + kp*2 + plane. Wp = packed words (pitch K words/row).
// ASRC: 0 = row-major A; 1 = fused LayerNorm rows (MTILES=2); 2 = k-major A = g_yt (MTILES=1)
// EPI : 0 = plain; 1 = +bias+pos+temb; 2 = += C (residual)
#define B_SZI (64*40)
#define SMEM_BM64  ((2*64*40 + 2*B_SZI)*4)
#define SMEM_BM128 ((2*128*40 + 2*B_SZI)*4 + 256*4)
template<int MTILES,int ASRC,int EPI>
__global__ void __launch_bounds__(256)
mma_gemm(const float* __restrict__ A, const unsigned* __restrict__ Wp,
         const float* __restrict__ lng, const float* __restrict__ lnb,
         const float* __restrict__ bias, const float* __restrict__ pos,
         const float* __restrict__ temb, float* __restrict__ C,
         int K, int N)
{
  constexpr int BM = 64*MTILES;
  constexpr int A_SZI = BM*40;
  extern __shared__ unsigned smem_u[];
  unsigned* uA = smem_u;                         // [buf][m][kp][plane]
  unsigned* uB = smem_u + 2*A_SZI;               // [buf][n][kp][plane]
  float* s_mu = (float*)(smem_u + 2*A_SZI + 2*B_SZI);
  float* s_rs = s_mu + 128;

  const int tid = threadIdx.x;
  const int m0 = blockIdx.y*BM, n0 = blockIdx.x*64;

  if (ASRC==1){
    int r = tid>>1, hf = tid&1;
    const float4* row = (const float4*)(A + (size_t)(m0+r)*K + hf*(K/2));
    float s=0.f, sq=0.f;
    for (int i=0;i<K/8;i++){ float4 v=row[i];
      s += v.x+v.y+v.z+v.w; sq += v.x*v.x+v.y*v.y+v.z*v.z+v.w*v.w; }
    s  += __shfl_xor_sync(0xffffffffu, s, 1);
    sq += __shfl_xor_sync(0xffffffffu, sq, 1);
    if (!hf){
      float muv = s/(float)K;
      float var = sq/(float)K - muv*muv;
      s_mu[r]=muv; s_rs[r]=rsqrtf(var+1e-5f);
    }
    __syncthreads();
  }

  // loader coords
  const int amr = tid>>3;            // ASRC 0/1: A row base
  const int akc = (tid&7)*4;         // ASRC 0/1: k offset (= word idx of kpair group)
  const int aq4 = (tid>>4)*4;        // ASRC 2: m quad base
  const int apd = (tid&15)*2;        // ASRC 2: local k (even)
  const int NK = K/32;
  const float* Ak = (ASRC==2) ? (A + (size_t)(m0>>8)*DI*LL + (m0&255)) : A;

  // initial chunk 0 into buf 0
  {
    if (ASRC==2){
      float4 v0 = *(const float4*)(Ak + (size_t)apd*LL + aq4);
      float4 v1 = *(const float4*)(Ak + (size_t)(apd+1)*LL + aq4);
      #pragma unroll
      for (int j=0;j<4;j++)
        store_split2(uA, (aq4+j)*40 + apd, (&v0.x)[j], (&v1.x)[j]);
    } else {
      float4 g4, b4;
      if (ASRC==1){ g4 = *(const float4*)(lng+akc); b4 = *(const float4*)(lnb+akc); }
      #pragma unroll
      for (int i=0;i<BM/32;i++){
        int m = amr + i*32;
        float4 v = *(const float4*)(A + (size_t)(m0+m)*K + akc);
        if (ASRC==1){
          float mu = s_mu[m], rs = s_rs[m];
          v.x=(v.x-mu)*rs*g4.x+b4.x; v.y=(v.y-mu)*rs*g4.y+b4.y;
          v.z=(v.z-mu)*rs*g4.z+b4.z; v.w=(v.w-mu)*rs*g4.w+b4.w;
        }
        store_split(uA, m*40 + akc, v);
      }
    }
    #pragma unroll
    for (int i=0;i<2;i++){
      int p = tid + i*256;
      int n = p>>3, kc4 = (p&7)*4;
      uint4 v = *(const uint4*)(Wp + (size_t)(n0+n)*K + kc4);
      *(uint4*)(uB + n*40 + kc4) = v;
    }
  }
  __syncthreads();

  const int lane = tid&31, wid = tid>>5;
  const int wm = (wid>>1)*(16*MTILES), wn = (wid&1)*32;
  const int g = lane>>2, tg = lane&3;
  float acc[MTILES][4][4] = {};

  float4 pa[ASRC==2?2:(BM/32)], pg4, pb4;
  uint4 pbu[2];
  for (int ks=0; ks<NK; ks++){
    const int buf = ks&1;
    if (ks+1 < NK){
      int k0 = (ks+1)*32;
      if (ASRC==2){
        pa[0] = *(const float4*)(Ak + (size_t)(k0+apd)*LL + aq4);
        pa[1] = *(const float4*)(Ak + (size_t)(k0+apd+1)*LL + aq4);
      } else {
        if (ASRC==1){ pg4 = *(const float4*)(lng+k0+akc); pb4 = *(const float4*)(lnb+k0+akc); }
        #pragma unroll
        for (int i=0;i<(ASRC==2?0:BM/32);i++)
          pa[i] = *(const float4*)(A + (size_t)(m0+amr+i*32)*K + k0 + akc);
      }
      #pragma unroll
      for (int i=0;i<2;i++){
        int p = tid + i*256;
        pbu[i] = *(const uint4*)(Wp + (size_t)(n0+(p>>3))*K + k0 + (p&7)*4);
      }
    }
    const unsigned* As_ = uA + buf*A_SZI;
    const unsigned* Bs_ = uB + buf*B_SZI;
    #pragma unroll
    for (int h=0; h<2; h++){
      const int kb = h*8;
      unsigned bh[4][2], bl[4][2];
      #pragma unroll
      for (int nt=0;nt<4;nt++){
        int nb = wn + nt*8 + g;
        uint2 p0 = *(const uint2*)&Bs_[nb*40 + (kb+tg)*2];
        uint2 p1 = *(const uint2*)&Bs_[nb*40 + (kb+tg+4)*2];
        bh[nt][0]=p0.x; bl[nt][0]=p0.y;
        bh[nt][1]=p1.x; bl[nt][1]=p1.y;
      }
      #pragma unroll
      for (int mt=0;mt<MTILES;mt++){
        int mb = wm + mt*16;
        uint2 q00 = *(const uint2*)&As_[(mb+g  )*40 + (kb+tg)*2];
        uint2 q10 = *(const uint2*)&As_[(mb+g+8)*40 + (kb+tg)*2];
        uint2 q01 = *(const uint2*)&As_[(mb+g  )*40 + (kb+tg+4)*2];
        uint2 q11 = *(const uint2*)&As_[(mb+g+8)*40 + (kb+tg+4)*2];
        unsigned ah[4] = {q00.x, q10.x, q01.x, q11.x};
        unsigned al[4] = {q00.y, q10.y, q01.y, q11.y};
        #pragma unroll
        for (int nt=0;nt<4;nt++){
          mma16(acc[mt][nt], ah, bh[nt][0], bh[nt][1]);
          mma16(acc[mt][nt], al, bh[nt][0], bh[nt][1]);
          mma16(acc[mt][nt], ah, bl[nt][0], bl[nt][1]);
        }
      }
    }
    if (ks+1 < NK){
      unsigned* dA = uA + (buf^1)*A_SZI;
      unsigned* dB = uB + (buf^1)*B_SZI;
      if (ASRC==2){
        #pragma unroll
        for (int j=0;j<4;j++)
          store_split2(dA, (aq4+j)*40 + apd, (&pa[0].x)[j], (&pa[1].x)[j]);
      } else {
        #pragma unroll
        for (int i=0;i<(ASRC==2?0:BM/32);i++){
          int m = amr + i*32;
          float4 v = pa[i];
          if (ASRC==1){
            float mu = s_mu[m], rs = s_rs[m];
            v.x=(v.x-mu)*rs*pg4.x+pb4.x; v.y=(v.y-mu)*rs*pg4.y+pb4.y;
            v.z=(v.z-mu)*rs*pg4.z+pb4.z; v.w=(v.w-mu)*rs*pg4.w+pb4.w;
          }
          store_split(dA, m*40 + akc, v);
        }
      }
      #pragma unroll
      for (int i=0;i<2;i++){
        int p = tid + i*256;
        *(uint4*)(dB + (p>>3)*40 + (p&7)*4) = pbu[i];
      }
    }
    __syncthreads();
  }

  // epilogue
  #pragma unroll
  for (int mt=0;mt<MTILES;mt++){
    #pragma unroll
    for (int nt=0;nt<4;nt++){
      int row = m0 + wm + mt*16 + g;
      int col = n0 + wn + nt*8 + tg*2;
      float2 v0 = make_float2(acc[mt][nt][0], acc[mt][nt][1]);
      float2 v1 = make_float2(acc[mt][nt][2], acc[mt][nt][3]);
      if (EPI==1){
        int l0i = row & 255, b0i = row >> 8;
        int l1i = (row+8) & 255, b1i = (row+8) >> 8;
        v0.x += bias[col]   + pos[(size_t)l0i*EE+col]   + temb[(size_t)b0i*EE+col];
        v0.y += bias[col+1] + pos[(size_t)l0i*EE+col+1] + temb[(size_t)b0i*EE+col+1];
        v1.x += bias[col]   + pos[(size_t)l1i*EE+col]   + temb[(size_t)b1i*EE+col];
        v1.y += bias[col+1] + pos[(size_t)l1i*EE+col+1] + temb[(size_t)b1i*EE+col+1];
      } else if (EPI==2){
        float2 o0 = *(float2*)(C + (size_t)row*N + col);
        float2 o1 = *(float2*)(C + (size_t)(row+8)*N + col);
        v0.x += o0.x; v0.y += o0.y; v1.x += o1.x; v1.y += o1.y;
      }
      *(float2*)(C + (size_t)row*N + col) = v0;
      *(float2*)(C + (size_t)(row+8)*N + col) = v1;
    }
  }
}

// ---------------- fused prep: causal-conv+SiLU, z-SiLU, x_proj, dt; transposed stores ----
__global__ void prep_kernel(const float* __restrict__ cw, const float* __restrict__ cb,
                            const float* __restrict__ xw,   // [48][512]
                            const float* __restrict__ dtw,  // [512][16]
                            const float* __restrict__ dtb){ // [512]
  __shared__ float us[8][513];
  __shared__ float pool[48*129];
  __shared__ float dbc_s[8][52];
  const int tid = threadIdx.x;            // 256
  const int b  = blockIdx.x >> 5;
  const int l0 = (blockIdx.x & 31) * 8;
  float* zsm = pool;
  #pragma unroll
  for (int r=0;r<16;r++){
    int idx = r*256 + tid;
    int d  = idx & 511;
    int ti = idx >> 9;
    int l  = l0 + ti;
    float acc = cb[d];
    #pragma unroll
    for (int j=0;j<4;j++){
      int ls = l + j - 3;
      if (ls >= 0) acc = fmaf(g_xz[((size_t)(b*LL + ls))*XZW + d], cw[d*4 + j], acc);
    }
    us[ti][d] = siluf(acc);
    float z = g_xz[((size_t)(b*LL + l))*XZW + DI + d];
    zsm[ti*516 + d] = siluf(z);
  }
  __syncthreads();
  #pragma unroll
  for (int rr=0;rr<2;rr++){
    int d = tid + rr*256;
    float4 v0, v1, w0, w1;
    v0.x=us[0][d]; v0.y=us[1][d]; v0.z=us[2][d]; v0.w=us[3][d];
    v1.x=us[4][d]; v1.y=us[5][d]; v1.z=us[6][d]; v1.w=us[7][d];
    w0.x=zsm[0*516+d]; w0.y=zsm[1*516+d]; w0.z=zsm[2*516+d]; w0.w=zsm[3*516+d];
    w1.x=zsm[4*516+d]; w1.y=zsm[5*516+d]; w1.z=zsm[6*516+d]; w1.w=zsm[7*516+d];
    float* up = g_ut + ((size_t)(b*DI + d))*LL + l0;
    *(float4*)up = v0; *(float4*)(up+4) = v1;
    float* zp = g_zs + ((size_t)(b*DI + d))*LL + l0;
    *(float4*)zp = w0; *(float4*)(zp+4) = w1;
  }
  const int ti = tid >> 5, lane = tid & 31;
  float accA = 0.f, accB = 0.f;
  for (int kt=0;kt<4;kt++){
    __syncthreads();
    #pragma unroll
    for (int i=0;i<6;i++){
      int f = (tid + i*256)*4;
      int j = f >> 7, c = f & 127;
      float4 v = *(const float4*)(xw + (size_t)j*DI + kt*128 + c);
      pool[j*129+c]=v.x; pool[j*129+c+1]=v.y; pool[j*129+c+2]=v.z; pool[j*129+c+3]=v.w;
    }
    __syncthreads();
    #pragma unroll 4
    for (int c=0;c<128;c++){
      float a = us[ti][kt*128 + c];
      accA = fmaf(a, pool[lane*129 + c], accA);
      if (lane < 16) accB = fmaf(a, pool[(32+lane)*129 + c], accB);
    }
  }
  __syncthreads();
  dbc_s[ti][lane] = accA;
  if (lane < 16) dbc_s[ti][32 + lane] = accB;
  __syncthreads();
  {
    int tti = tid >> 5, jj = tid & 31;
    g_bc[((size_t)(b*LL) + l0 + tti)*32 + jj] = dbc_s[tti][16 + jj];
  }
  #pragma unroll
  for (int r=0;r<16;r++){
    int idx = r*256 + tid;
    int d  = idx & 511;
    int ti2 = idx >> 9;
    const float* dbp = dbc_s[ti2];
    const float4* dw4 = (const float4*)(dtw + (size_t)d*16);
    float4 w0 = dw4[0], w1 = dw4[1], w2 = dw4[2], w3 = dw4[3];
    float acc = dtb[d];
    acc=fmaf(dbp[0],w0.x,acc);  acc=fmaf(dbp[1],w0.y,acc);  acc=fmaf(dbp[2],w0.z,acc);  acc=fmaf(dbp[3],w0.w,acc);
    acc=fmaf(dbp[4],w1.x,acc);  acc=fmaf(dbp[5],w1.y,acc);  acc=fmaf(dbp[6],w1.z,acc);  acc=fmaf(dbp[7],w1.w,acc);
    acc=fmaf(dbp[8],w2.x,acc);  acc=fmaf(dbp[9],w2.y,acc);  acc=fmaf(dbp[10],w2.z,acc); acc=fmaf(dbp[11],w2.w,acc);
    acc=fmaf(dbp[12],w3.x,acc); acc=fmaf(dbp[13],w3.y,acc); acc=fmaf(dbp[14],w3.z,acc); acc=fmaf(dbp[15],w3.w,acc);
    us[ti2][d] = (acc > 20.f) ? acc : log1pf(__expf(acc));
  }
  __syncthreads();
  #pragma unroll
  for (int rr=0;rr<2;rr++){
    int d = tid + rr*256;
    float4 v0, v1;
    v0.x=us[0][d]; v0.y=us[1][d]; v0.z=us[2][d]; v0.w=us[3][d];
    v1.x=us[4][d]; v1.y=us[5][d]; v1.z=us[6][d]; v1.w=us[7][d];
    float* dp = g_dtt + ((size_t)(b*DI + d))*LL + l0;
    *(float4*)dp = v0; *(float4*)(dp+4) = v1;
  }
}

// ---------------- SSM chunked parallel scan: block = one (b,d) ----------------
__global__ void ssm_scan(const float* __restrict__ Alog, const float* __restrict__ Dp){
  __shared__ float sA[16][17], sB[16][17], sH[16][17];
  __shared__ float sv[256][17];
  const int bd = blockIdx.x;
  const int b = bd >> 9, d = bd & 511;
  const int tid = threadIdx.x;
  const int c = tid >> 4, s = tid & 15;
  const float As = -__expf(Alog[d*16 + s]);
  const float* dtp = g_dtt + ((size_t)(b*DI + d))*LL + c*16;
  const float* up  = g_ut  + ((size_t)(b*DI + d))*LL + c*16;
  const float* bcp = g_bc + ((size_t)(b*LL + c*16))*32 + s;
  float a[16], bv[16];
  #pragma unroll
  for (int i=0;i<16;i++){
    float dt = dtp[i], u = up[i];
    float Bm = bcp[i*32];
    a[i]  = __expf(dt * As);
    bv[i] = dt * u * Bm;
  }
  float Ap = 1.f, Bf = 0.f;
  #pragma unroll
  for (int i=0;i<16;i++){ Bf = fmaf(a[i], Bf, bv[i]); Ap *= a[i]; }
  sA[c][s] = Ap; sB[c][s] = Bf;
  __syncthreads();
  if (tid < 16){
    float h = 0.f;
    #pragma unroll
    for (int cc=0;cc<16;cc++){
      sH[cc][tid] = h;
      h = fmaf(sA[cc][tid], h, sB[cc][tid]);
    }
  }
  __syncthreads();
  float h = sH[c][s];
  #pragma unroll
  for (int i=0;i<16;i++){
    h = fmaf(a[i], h, bv[i]);
    float Cm = bcp[i*32 + 16];
    sv[c*16 + i][s] = h * Cm;
  }
  __syncthreads();
  float y = 0.f;
  #pragma unroll
  for (int ss=0;ss<16;ss++) y += sv[tid][ss];
  float u_t = g_ut[((size_t)(b*DI + d))*LL + tid];
  float zs  = g_zs[((size_t)(b*DI + d))*LL + tid];
  g_yt[((size_t)(b*DI + d))*LL + tid] = (y + u_t * Dp[d]) * zs;
}

// ---------------- feat[b,e,l] = h[b,l,e] ----------------
__global__ void feat_kernel(){
  __shared__ float tile[32][33];
  int b = blockIdx.z; int t0 = blockIdx.x*32; int e0 = blockIdx.y*32;
  int tx = threadIdx.x, ty = threadIdx.y;
  #pragma unroll
  for (int i=0;i<32;i+=8)
    tile[ty+i][tx] = g_h[((size_t)b*LL + t0+ty+i)*EE + e0+tx];
  __syncthreads();
  #pragma unroll
  for (int i=0;i<32;i+=8)
    g_feat[((size_t)b*EE + e0+ty+i)*LL + t0+tx] = tile[tx][ty+i];
}

// ---------------- ConvTranspose2d stride2 k2 ----------------
template<int C,int O,int OGRP,int GELU>
__global__ void convt_kernel(const float* __restrict__ x, const float* __restrict__ w,
                             const float* __restrict__ bias, float* __restrict__ out,
                             int Hin, int Win){
  int idx = blockIdx.x*blockDim.x + threadIdx.x;
  int w_ = idx % Win; int tmp = idx / Win;
  int h_ = tmp % Hin; tmp /= Hin;
  int og = tmp % (O/OGRP); int b = tmp / (O/OGRP);
  int o0 = og*OGRP;
  float acc[OGRP][4];
  #pragma unroll
  for (int g=0;g<OGRP;g++){
    float bvv = bias[o0+g];
    acc[g][0]=bvv; acc[g][1]=bvv; acc[g][2]=bvv; acc[g][3]=bvv;
  }
  const float* xp = x + ((size_t)b*C*Hin + h_)*Win + w_;
  const float* wp = w + o0*4;
  size_t xstride = (size_t)Hin*Win;
  #pragma unroll 4
  for (int c=0;c<C;c++){
    float xv = __ldg(xp + c*xstride);
    const float4* w4 = (const float4*)(wp + (size_t)c*O*4);
    #pragma unroll
    for (int g=0;g<OGRP;g++){
      float4 wt = __ldg(w4 + g);
      acc[g][0]=fmaf(xv,wt.x,acc[g][0]); acc[g][1]=fmaf(xv,wt.y,acc[g][1]);
      acc[g][2]=fmaf(xv,wt.z,acc[g][2]); acc[g][3]=fmaf(xv,wt.w,acc[g][3]);
    }
  }
  int Ho = 2*Hin, Wo = 2*Win;
  #pragma unroll
  for (int g=0;g<OGRP;g++){
    float r00=acc[g][0], r01=acc[g][1], r10=acc[g][2], r11=acc[g][3];
    if (GELU){ r00=geluf(r00); r01=geluf(r01); r10=geluf(r10); r11=geluf(r11); }
    float* op = out + (((size_t)b*O + o0+g)*Ho + 2*h_)*(size_t)Wo + 2*w_;
    *(float2*)op        = make_float2(r00,r01);
    *(float2*)(op + Wo) = make_float2(r10,r11);
  }
}

// ---------------- launch ----------------
extern "C" void kernel_launch(void* const* d_in, const int* in_sizes, int n_in,
                              void* d_out, int out_size){
  const float* x       = (const float*)d_in[0];
  const int*   t       = (const int*)d_in[1];
  const float* time_w1 = (const float*)d_in[2];
  const float* time_b1 = (const float*)d_in[3];
  const float* time_w2 = (const float*)d_in[4];
  const float* time_b2 = (const float*)d_in[5];
  const float* patch_w = (const float*)d_in[6];
  const float* patch_b = (const float*)d_in[7];
  const float* pos     = (const float*)d_in[8];
  const float* ln_g    = (const float*)d_in[9];
  const float* ln_b    = (const float*)d_in[10];
  const float* in_proj = (const float*)d_in[11];
  const float* conv_w  = (const float*)d_in[12];
  const float* conv_b  = (const float*)d_in[13];
  const float* x_proj  = (const float*)d_in[14];
  const float* dt_w    = (const float*)d_in[15];
  const float* dt_b    = (const float*)d_in[16];
  const float* A_log   = (const float*)d_in[17];
  const float* Dp      = (const float*)d_in[18];
  const float* out_proj= (const float*)d_in[19];
  const float* dw1 = (const float*)d_in[20];
  const float* db1 = (const float*)d_in[21];
  const float* dw2 = (const float*)d_in[22];
  const float* db2 = (const float*)d_in[23];
  const float* dw3 = (const float*)d_in[24];
  const float* db3 = (const float*)d_in[25];
  const float* dw4 = (const float*)d_in[26];
  const float* db4 = (const float*)d_in[27];

  float *p_patches,*p_h,*p_xz,*p_temb,*p_yt,*p_feat,*p_d1,*p_d2,*p_d3;
  unsigned *p_wpi,*p_wpo,*p_wpp;
  cudaGetSymbolAddress((void**)&p_patches, g_patches);
  cudaGetSymbolAddress((void**)&p_h, g_h);
  cudaGetSymbolAddress((void**)&p_xz, g_xz);
  cudaGetSymbolAddress((void**)&p_temb, g_temb);
  cudaGetSymbolAddress((void**)&p_yt, g_yt);
  cudaGetSymbolAddress((void**)&p_feat, g_feat);
  cudaGetSymbolAddress((void**)&p_d1, g_d1);
  cudaGetSymbolAddress((void**)&p_d2, g_d2);
  cudaGetSymbolAddress((void**)&p_d3, g_d3);
  cudaGetSymbolAddress((void**)&p_wpi, g_wp_in);
  cudaGetSymbolAddress((void**)&p_wpo, g_wp_out);
  cudaGetSymbolAddress((void**)&p_wpp, g_wp_patch);

  cudaFuncSetAttribute(mma_gemm<1,0,1>, cudaFuncAttributeMaxDynamicSharedMemorySize, SMEM_BM64);
  cudaFuncSetAttribute(mma_gemm<2,1,0>, cudaFuncAttributeMaxDynamicSharedMemorySize, SMEM_BM128);
  cudaFuncSetAttribute(mma_gemm<1,2,2>, cudaFuncAttributeMaxDynamicSharedMemorySize, SMEM_BM64);

  // pre-pack weights into interleaved bf16 hi/lo word format
  wpack_kernel<<<(DEPTH*XZW*EE/2 + 255)/256, 256>>>(in_proj, p_wpi, DEPTH*XZW*EE/2);
  wpack_kernel<<<(DEPTH*EE*DI/2 + 255)/256, 256>>>(out_proj, p_wpo, DEPTH*EE*DI/2);
  wpack_kernel<<<(EE*512/2 + 255)/256, 256>>>(patch_w, p_wpp, EE*512/2);

  time_emb_kernel<<<BB, EE>>>(t, time_w1, time_b1, time_w2, time_b2);
  patch_gather_kernel<<<(NTOK*512)/256, 256>>>(x);
  // patch embed: 2048x256x512, epi = bias+pos+temb  (BM=64 -> 128 blocks)
  mma_gemm<1,0,1><<<dim3(EE/64, NTOK/64), 256, SMEM_BM64>>>(
      p_patches, p_wpp, nullptr, nullptr, patch_b, pos, p_temb, p_h, 512, EE);

  for (int i=0;i<DEPTH;i++){
    // in_proj with fused LN: 2048x1024x256 (BM=128 -> 256 blocks)
    mma_gemm<2,1,0><<<dim3(XZW/64, NTOK/128), 256, SMEM_BM128>>>(
        p_h, p_wpi + (size_t)i*XZW*EE,
        ln_g + (size_t)i*EE, ln_b + (size_t)i*EE,
        nullptr, nullptr, nullptr, p_xz, EE, XZW);
    prep_kernel<<<NTOK/8, 256>>>(conv_w + (size_t)i*DI*DCN, conv_b + (size_t)i*DI,
                                 x_proj + (size_t)i*48*DI,
                                 dt_w + (size_t)i*DI*DTRN, dt_b + (size_t)i*DI);
    ssm_scan<<<BB*DI, 256>>>(A_log + (size_t)i*DI*DS, Dp + (size_t)i*DI);
    // out_proj reading g_yt k-major + residual: 2048x256x512 (BM=64 -> 128 blocks)
    mma_gemm<1,2,2><<<dim3(EE/64, NTOK/64), 256, SMEM_BM64>>>(
        p_yt, p_wpo + (size_t)i*EE*DI,
        nullptr, nullptr, nullptr, nullptr, nullptr, p_h, DI, EE);
  }

  feat_kernel<<<dim3(LL/32, EE/32, BB), dim3(32,8)>>>();
  convt_kernel<256,128,4,1><<<(BB*(128/4)*16*16)/256, 256>>>(p_feat, dw1, db1, p_d1, 16, 16);
  convt_kernel<128,64,4,1><<<(BB*(64/4)*32*32)/256, 256>>>(p_d1, dw2, db2, p_d2, 32, 32);
  convt_kernel<64,32,4,1><<<(BB*(32/4)*64*64)/256, 256>>>(p_d2, dw3, db3, p_d3, 64, 64);
  convt_kernel<32,1,1,0><<<(BB*1*128*128)/256, 256>>>(p_d3, dw4, db4, (float*)d_out, 128, 128);
}

// round 12
// speedup vs baseline: 1.1764x; 1.1764x over previous
#include <cuda_runtime.h>
#include <cuda_bf16.h>
#include <math.h>

#define BB 8
#define IMG 256
#define INCH 2
#define PSZ 16
#define EE 256
#define DEPTH 8
#define HPN 16
#define LL 256
#define DI 512
#define DS 16
#define DTRN 16
#define DCN 4
#define NTOK 2048          // B*L
#define XZW 1024           // 2*DI

// ---------------- scratch ----------------
__device__ float g_temb[BB*EE];
__device__ float g_h[NTOK*EE];
__device__ float g_patches[NTOK*512];
__device__ float g_xz[NTOK*XZW];
__device__ float g_ut[BB*DI*LL];    // u transposed [b][d][t]
__device__ float g_dtt[BB*DI*LL];   // dt transposed [b][d][t]
__device__ float g_zs[BB*DI*LL];    // silu(z) transposed [b][d][t]
__device__ float g_bc[NTOK*32];     // B[16],C[16] per token
__device__ float g_yt[BB*DI*LL];    // y transposed [b][d][t]
__device__ float g_d1[BB*128*32*32];   // NHWC [b][1024][128]
__device__ float g_d2[BB*64*64*64];    // NHWC [b][4096][64]
__device__ float g_d3[BB*32*128*128];  // NHWC [b][16384][32]
// packed bf16 hi/lo weight buffers (word idx = n*K + k)
__device__ unsigned g_wp_in[DEPTH*XZW*EE];
__device__ unsigned g_wp_out[DEPTH*EE*DI];
__device__ unsigned g_wp_patch[EE*512];
__device__ unsigned g_wp_d1[512*256];
__device__ unsigned g_wp_d2[256*128];
__device__ unsigned g_wp_d3[128*64];

__device__ __forceinline__ float geluf(float v){ return 0.5f*v*(1.0f+erff(v*0.70710678118654752f)); }
__device__ __forceinline__ float siluf(float v){ return v/(1.0f+__expf(-v)); }

__device__ __forceinline__ void mma16(float* d, const unsigned* a, unsigned b0, unsigned b1){
  asm volatile("mma.sync.aligned.m16n8k16.row.col.f32.bf16.bf16.f32 "
    "{%0,%1,%2,%3}, {%4,%5,%6,%7}, {%8,%9}, {%0,%1,%2,%3};"
    : "+f"(d[0]),"+f"(d[1]),"+f"(d[2]),"+f"(d[3])
    : "r"(a[0]),"r"(a[1]),"r"(a[2]),"r"(a[3]), "r"(b0),"r"(b1));
}

// split float4 (4 consecutive k) into interleaved {hi,lo,hi,lo} words; one STS.128
__device__ __forceinline__ void store_split(unsigned* base, int widx, float4 v){
  __nv_bfloat162 h0 = __floats2bfloat162_rn(v.x, v.y);
  __nv_bfloat162 h1 = __floats2bfloat162_rn(v.z, v.w);
  float r0 = v.x - __bfloat162float(h0.x);
  float r1 = v.y - __bfloat162float(h0.y);
  float r2 = v.z - __bfloat162float(h1.x);
  float r3 = v.w - __bfloat162float(h1.y);
  __nv_bfloat162 l0 = __floats2bfloat162_rn(r0, r1);
  __nv_bfloat162 l1 = __floats2bfloat162_rn(r2, r3);
  uint4 w;
  w.x = *(unsigned*)&h0; w.y = *(unsigned*)&l0;
  w.z = *(unsigned*)&h1; w.w = *(unsigned*)&l1;
  *(uint4*)(base + widx) = w;
}
__device__ __forceinline__ void store_split2(unsigned* base, int widx, float a0, float a1){
  __nv_bfloat162 h = __floats2bfloat162_rn(a0, a1);
  float r0 = a0 - __bfloat162float(h.x);
  float r1 = a1 - __bfloat162float(h.y);
  __nv_bfloat162 l = __floats2bfloat162_rn(r0, r1);
  uint2 w; w.x = *(unsigned*)&h; w.y = *(unsigned*)&l;
  *(uint2*)(base + widx) = w;
}
__device__ __forceinline__ uint2 pack_pair(float a0, float a1){
  __nv_bfloat162 h = __floats2bfloat162_rn(a0, a1);
  float r0 = a0 - __bfloat162float(h.x);
  float r1 = a1 - __bfloat162float(h.y);
  __nv_bfloat162 l = __floats2bfloat162_rn(r0, r1);
  uint2 w; w.x = *(unsigned*)&h; w.y = *(unsigned*)&l;
  return w;
}

// ---------------- weight pre-pack: row-major [N][K] float -> packed ----------------
__global__ void wpack_kernel(const float* __restrict__ W, unsigned* __restrict__ P, int total_pairs){
  int idx = blockIdx.x*blockDim.x + threadIdx.x;
  if (idx >= total_pairs) return;
  float2 v = *(const float2*)(W + (size_t)idx*2);
  *(uint2*)(P + (size_t)idx*2) = pack_pair(v.x, v.y);
}
// transposed pack: W is [K][N] row-major -> P[n][k-words]
__global__ void wpack_t_kernel(const float* __restrict__ W, unsigned* __restrict__ P, int N, int K){
  int idx = blockIdx.x*blockDim.x + threadIdx.x;
  int total = N*(K/2);
  if (idx >= total) return;
  int n = idx / (K/2), kp = idx % (K/2);
  float a0 = W[(size_t)(2*kp)*N + n];
  float a1 = W[(size_t)(2*kp+1)*N + n];
  *(uint2*)(P + (size_t)n*K + 2*kp) = pack_pair(a0, a1);
}

// ---------------- time embedding: grid (B, 8), block 256 ----------------
__global__ void time_emb_kernel(const int* __restrict__ t, const float* __restrict__ w1,
                                const float* __restrict__ b1, const float* __restrict__ w2,
                                const float* __restrict__ b2){
  __shared__ float hdn[EE];
  __shared__ float part[8][33];
  int b = blockIdx.x, jg = blockIdx.y;
  int tid = threadIdx.x;
  float tf = (float)t[b];
  hdn[tid] = geluf(tf*w1[tid] + b1[tid]);
  __syncthreads();
  int j = jg*32 + (tid & 31);
  int kg = tid >> 5;
  float acc = 0.f;
  #pragma unroll 8
  for (int k = kg*32; k < kg*32+32; k++) acc = fmaf(hdn[k], w2[k*EE + j], acc);
  part[kg][tid & 31] = acc;
  __syncthreads();
  if (tid < 32){
    int jj = jg*32 + tid;
    float s = b2[jj];
    #pragma unroll
    for (int i=0;i<8;i++) s += part[i][tid];
    g_temb[b*EE + jj] = s;
  }
}

// ---------------- im2col patch gather ----------------
__global__ void patch_gather_kernel(const float* __restrict__ x){
  int idx = blockIdx.x*blockDim.x + threadIdx.x;
  int k = idx & 511; int tok = idx >> 9;
  int l = tok & (LL-1); int b = tok >> 8;
  int c = k >> 8; int rem = k & 255; int p = rem >> 4; int q = rem & 15;
  int hp = l >> 4; int wp = l & 15;
  g_patches[idx] = x[(((size_t)(b*INCH + c))*IMG + hp*PSZ + p)*IMG + wp*PSZ + q];
}

// ================= bf16x3 tensor-core GEMM =================
// ASRC: 0 = row-major A; 1 = fused LayerNorm rows (MTILES=2); 2 = k-major A (g_yt, MTILES=1)
// EPI : 0 = plain; 1 = +bias+pos+temb; 2 = += C (residual);
//       3 = +bias[o] + GELU + NHWC convT scatter (lgRPB=log2 rows/batch, lgW=log2 Wspatial)
#define B_SZI (64*40)
#define SMEM_BM64  ((2*64*40 + 2*B_SZI)*4)
#define SMEM_BM128 ((2*128*40 + 2*B_SZI)*4 + 256*4)
template<int MTILES,int ASRC,int EPI>
__global__ void __launch_bounds__(256)
mma_gemm(const float* __restrict__ A, const unsigned* __restrict__ Wp,
         const float* __restrict__ lng, const float* __restrict__ lnb,
         const float* __restrict__ bias, const float* __restrict__ pos,
         const float* __restrict__ temb, float* __restrict__ C,
         int K, int N, int lgRPB = 0, int lgW = 0)
{
  constexpr int BM = 64*MTILES;
  constexpr int A_SZI = BM*40;
  extern __shared__ unsigned smem_u[];
  unsigned* uA = smem_u;
  unsigned* uB = smem_u + 2*A_SZI;
  float* s_mu = (float*)(smem_u + 2*A_SZI + 2*B_SZI);
  float* s_rs = s_mu + 128;

  const int tid = threadIdx.x;
  const int m0 = blockIdx.y*BM, n0 = blockIdx.x*64;

  if (ASRC==1){
    int r = tid>>1, hf = tid&1;
    const float4* row = (const float4*)(A + (size_t)(m0+r)*K + hf*(K/2));
    float s=0.f, sq=0.f;
    for (int i=0;i<K/8;i++){ float4 v=row[i];
      s += v.x+v.y+v.z+v.w; sq += v.x*v.x+v.y*v.y+v.z*v.z+v.w*v.w; }
    s  += __shfl_xor_sync(0xffffffffu, s, 1);
    sq += __shfl_xor_sync(0xffffffffu, sq, 1);
    if (!hf){
      float muv = s/(float)K;
      float var = sq/(float)K - muv*muv;
      s_mu[r]=muv; s_rs[r]=rsqrtf(var+1e-5f);
    }
    __syncthreads();
  }

  const int amr = tid>>3;
  const int akc = (tid&7)*4;
  const int aq4 = (tid>>4)*4;
  const int apd = (tid&15)*2;
  const int NK = K/32;
  const float* Ak = (ASRC==2) ? (A + (size_t)(m0>>8)*DI*LL + (m0&255)) : A;

  {
    if (ASRC==2){
      float4 v0 = *(const float4*)(Ak + (size_t)apd*LL + aq4);
      float4 v1 = *(const float4*)(Ak + (size_t)(apd+1)*LL + aq4);
      #pragma unroll
      for (int j=0;j<4;j++)
        store_split2(uA, (aq4+j)*40 + apd, (&v0.x)[j], (&v1.x)[j]);
    } else {
      float4 g4, b4;
      if (ASRC==1){ g4 = *(const float4*)(lng+akc); b4 = *(const float4*)(lnb+akc); }
      #pragma unroll
      for (int i=0;i<BM/32;i++){
        int m = amr + i*32;
        float4 v = *(const float4*)(A + (size_t)(m0+m)*K + akc);
        if (ASRC==1){
          float mu = s_mu[m], rs = s_rs[m];
          v.x=(v.x-mu)*rs*g4.x+b4.x; v.y=(v.y-mu)*rs*g4.y+b4.y;
          v.z=(v.z-mu)*rs*g4.z+b4.z; v.w=(v.w-mu)*rs*g4.w+b4.w;
        }
        store_split(uA, m*40 + akc, v);
      }
    }
    #pragma unroll
    for (int i=0;i<2;i++){
      int p = tid + i*256;
      int n = p>>3, kc4 = (p&7)*4;
      uint4 v = *(const uint4*)(Wp + (size_t)(n0+n)*K + kc4);
      *(uint4*)(uB + n*40 + kc4) = v;
    }
  }
  __syncthreads();

  const int lane = tid&31, wid = tid>>5;
  const int wm = (wid>>1)*(16*MTILES), wn = (wid&1)*32;
  const int g = lane>>2, tg = lane&3;
  float acc[MTILES][4][4] = {};

  float4 pa[ASRC==2?2:(BM/32)], pg4, pb4;
  uint4 pbu[2];
  for (int ks=0; ks<NK; ks++){
    const int buf = ks&1;
    if (ks+1 < NK){
      int k0 = (ks+1)*32;
      if (ASRC==2){
        pa[0] = *(const float4*)(Ak + (size_t)(k0+apd)*LL + aq4);
        pa[1] = *(const float4*)(Ak + (size_t)(k0+apd+1)*LL + aq4);
      } else {
        if (ASRC==1){ pg4 = *(const float4*)(lng+k0+akc); pb4 = *(const float4*)(lnb+k0+akc); }
        #pragma unroll
        for (int i=0;i<(ASRC==2?0:BM/32);i++)
          pa[i] = *(const float4*)(A + (size_t)(m0+amr+i*32)*K + k0 + akc);
      }
      #pragma unroll
      for (int i=0;i<2;i++){
        int p = tid + i*256;
        pbu[i] = *(const uint4*)(Wp + (size_t)(n0+(p>>3))*K + k0 + (p&7)*4);
      }
    }
    const unsigned* As_ = uA + buf*A_SZI;
    const unsigned* Bs_ = uB + buf*B_SZI;
    #pragma unroll
    for (int h=0; h<2; h++){
      const int kb = h*8;
      unsigned bh[4][2], bl[4][2];
      #pragma unroll
      for (int nt=0;nt<4;nt++){
        int nb = wn + nt*8 + g;
        uint2 p0 = *(const uint2*)&Bs_[nb*40 + (kb+tg)*2];
        uint2 p1 = *(const uint2*)&Bs_[nb*40 + (kb+tg+4)*2];
        bh[nt][0]=p0.x; bl[nt][0]=p0.y;
        bh[nt][1]=p1.x; bl[nt][1]=p1.y;
      }
      #pragma unroll
      for (int mt=0;mt<MTILES;mt++){
        int mb = wm + mt*16;
        uint2 q00 = *(const uint2*)&As_[(mb+g  )*40 + (kb+tg)*2];
        uint2 q10 = *(const uint2*)&As_[(mb+g+8)*40 + (kb+tg)*2];
        uint2 q01 = *(const uint2*)&As_[(mb+g  )*40 + (kb+tg+4)*2];
        uint2 q11 = *(const uint2*)&As_[(mb+g+8)*40 + (kb+tg+4)*2];
        unsigned ah[4] = {q00.x, q10.x, q01.x, q11.x};
        unsigned al[4] = {q00.y, q10.y, q01.y, q11.y};
        #pragma unroll
        for (int nt=0;nt<4;nt++){
          mma16(acc[mt][nt], ah, bh[nt][0], bh[nt][1]);
          mma16(acc[mt][nt], al, bh[nt][0], bh[nt][1]);
          mma16(acc[mt][nt], ah, bl[nt][0], bl[nt][1]);
        }
      }
    }
    if (ks+1 < NK){
      unsigned* dA = uA + (buf^1)*A_SZI;
      unsigned* dB = uB + (buf^1)*B_SZI;
      if (ASRC==2){
        #pragma unroll
        for (int j=0;j<4;j++)
          store_split2(dA, (aq4+j)*40 + apd, (&pa[0].x)[j], (&pa[1].x)[j]);
      } else {
        #pragma unroll
        for (int i=0;i<(ASRC==2?0:BM/32);i++){
          int m = amr + i*32;
          float4 v = pa[i];
          if (ASRC==1){
            float mu = s_mu[m], rs = s_rs[m];
            v.x=(v.x-mu)*rs*pg4.x+pb4.x; v.y=(v.y-mu)*rs*pg4.y+pb4.y;
            v.z=(v.z-mu)*rs*pg4.z+pb4.z; v.w=(v.w-mu)*rs*pg4.w+pb4.w;
          }
          store_split(dA, m*40 + akc, v);
        }
      }
      #pragma unroll
      for (int i=0;i<2;i++){
        int p = tid + i*256;
        *(uint4*)(dB + (p>>3)*40 + (p&7)*4) = pbu[i];
      }
    }
    __syncthreads();
  }

  // epilogue
  #pragma unroll
  for (int mt=0;mt<MTILES;mt++){
    #pragma unroll
    for (int nt=0;nt<4;nt++){
      int row = m0 + wm + mt*16 + g;
      int col = n0 + wn + nt*8 + tg*2;
      float2 v0 = make_float2(acc[mt][nt][0], acc[mt][nt][1]);
      float2 v1 = make_float2(acc[mt][nt][2], acc[mt][nt][3]);
      if (EPI==3){
        // convT scatter: col = o*4 + p*2 + q -> NHWC [b][(2h+p)*2W+(2w+q)][o], + bias + gelu
        float vv[4] = {v0.x, v0.y, v1.x, v1.y};
        int rr[4] = {row, row, row+8, row+8};
        int cc[4] = {col, col+1, col, col+1};
        int O = N >> 2;
        int rpbm = (1<<lgRPB) - 1, wm_ = (1<<lgW) - 1;
        #pragma unroll
        for (int e=0;e<4;e++){
          int o = cc[e]>>2, p = (cc[e]>>1)&1, q = cc[e]&1;
          int bb_ = rr[e]>>lgRPB, hw = rr[e] & rpbm;
          int hh = hw>>lgW, ww = hw & wm_;
          size_t pix = ((size_t)bb_<<(lgRPB+2)) + (size_t)((2*hh+p)<<(lgW+1)) + (2*ww+q);
          C[pix*O + o] = geluf(vv[e] + bias[o]);
        }
      } else {
        if (EPI==1){
          int l0i = row & 255, b0i = row >> 8;
          int l1i = (row+8) & 255, b1i = (row+8) >> 8;
          v0.x += bias[col]   + pos[(size_t)l0i*EE+col]   + temb[(size_t)b0i*EE+col];
          v0.y += bias[col+1] + pos[(size_t)l0i*EE+col+1] + temb[(size_t)b0i*EE+col+1];
          v1.x += bias[col]   + pos[(size_t)l1i*EE+col]   + temb[(size_t)b1i*EE+col];
          v1.y += bias[col+1] + pos[(size_t)l1i*EE+col+1] + temb[(size_t)b1i*EE+col+1];
        } else if (EPI==2){
          float2 o0 = *(float2*)(C + (size_t)row*N + col);
          float2 o1 = *(float2*)(C + (size_t)(row+8)*N + col);
          v0.x += o0.x; v0.y += o0.y; v1.x += o1.x; v1.y += o1.y;
        }
        *(float2*)(C + (size_t)row*N + col) = v0;
        *(float2*)(C + (size_t)(row+8)*N + col) = v1;
      }
    }
  }
}

// ---------------- fused prep: causal-conv+SiLU, z-SiLU, x_proj, dt; transposed stores ----
__global__ void prep_kernel(const float* __restrict__ cw, const float* __restrict__ cb,
                            const float* __restrict__ xw,
                            const float* __restrict__ dtw,
                            const float* __restrict__ dtb){
  __shared__ float us[8][513];
  __shared__ float pool[48*129];
  __shared__ float dbc_s[8][52];
  const int tid = threadIdx.x;
  const int b  = blockIdx.x >> 5;
  const int l0 = (blockIdx.x & 31) * 8;
  float* zsm = pool;
  #pragma unroll
  for (int r=0;r<16;r++){
    int idx = r*256 + tid;
    int d  = idx & 511;
    int ti = idx >> 9;
    int l  = l0 + ti;
    float acc = cb[d];
    #pragma unroll
    for (int j=0;j<4;j++){
      int ls = l + j - 3;
      if (ls >= 0) acc = fmaf(g_xz[((size_t)(b*LL + ls))*XZW + d], cw[d*4 + j], acc);
    }
    us[ti][d] = siluf(acc);
    float z = g_xz[((size_t)(b*LL + l))*XZW + DI + d];
    zsm[ti*516 + d] = siluf(z);
  }
  __syncthreads();
  #pragma unroll
  for (int rr=0;rr<2;rr++){
    int d = tid + rr*256;
    float4 v0, v1, w0, w1;
    v0.x=us[0][d]; v0.y=us[1][d]; v0.z=us[2][d]; v0.w=us[3][d];
    v1.x=us[4][d]; v1.y=us[5][d]; v1.z=us[6][d]; v1.w=us[7][d];
    w0.x=zsm[0*516+d]; w0.y=zsm[1*516+d]; w0.z=zsm[2*516+d]; w0.w=zsm[3*516+d];
    w1.x=zsm[4*516+d]; w1.y=zsm[5*516+d]; w1.z=zsm[6*516+d]; w1.w=zsm[7*516+d];
    float* up = g_ut + ((size_t)(b*DI + d))*LL + l0;
    *(float4*)up = v0; *(float4*)(up+4) = v1;
    float* zp = g_zs + ((size_t)(b*DI + d))*LL + l0;
    *(float4*)zp = w0; *(float4*)(zp+4) = w1;
  }
  const int ti = tid >> 5, lane = tid & 31;
  float accA = 0.f, accB = 0.f;
  for (int kt=0;kt<4;kt++){
    __syncthreads();
    #pragma unroll
    for (int i=0;i<6;i++){
      int f = (tid + i*256)*4;
      int j = f >> 7, c = f & 127;
      float4 v = *(const float4*)(xw + (size_t)j*DI + kt*128 + c);
      pool[j*129+c]=v.x; pool[j*129+c+1]=v.y; pool[j*129+c+2]=v.z; pool[j*129+c+3]=v.w;
    }
    __syncthreads();
    #pragma unroll 4
    for (int c=0;c<128;c++){
      float a = us[ti][kt*128 + c];
      accA = fmaf(a, pool[lane*129 + c], accA);
      if (lane < 16) accB = fmaf(a, pool[(32+lane)*129 + c], accB);
    }
  }
  __syncthreads();
  dbc_s[ti][lane] = accA;
  if (lane < 16) dbc_s[ti][32 + lane] = accB;
  __syncthreads();
  {
    int tti = tid >> 5, jj = tid & 31;
    g_bc[((size_t)(b*LL) + l0 + tti)*32 + jj] = dbc_s[tti][16 + jj];
  }
  #pragma unroll
  for (int r=0;r<16;r++){
    int idx = r*256 + tid;
    int d  = idx & 511;
    int ti2 = idx >> 9;
    const float* dbp = dbc_s[ti2];
    const float4* dw4 = (const float4*)(dtw + (size_t)d*16);
    float4 w0 = dw4[0], w1 = dw4[1], w2 = dw4[2], w3 = dw4[3];
    float acc = dtb[d];
    acc=fmaf(dbp[0],w0.x,acc);  acc=fmaf(dbp[1],w0.y,acc);  acc=fmaf(dbp[2],w0.z,acc);  acc=fmaf(dbp[3],w0.w,acc);
    acc=fmaf(dbp[4],w1.x,acc);  acc=fmaf(dbp[5],w1.y,acc);  acc=fmaf(dbp[6],w1.z,acc);  acc=fmaf(dbp[7],w1.w,acc);
    acc=fmaf(dbp[8],w2.x,acc);  acc=fmaf(dbp[9],w2.y,acc);  acc=fmaf(dbp[10],w2.z,acc); acc=fmaf(dbp[11],w2.w,acc);
    acc=fmaf(dbp[12],w3.x,acc); acc=fmaf(dbp[13],w3.y,acc); acc=fmaf(dbp[14],w3.z,acc); acc=fmaf(dbp[15],w3.w,acc);
    us[ti2][d] = (acc > 20.f) ? acc : log1pf(__expf(acc));
  }
  __syncthreads();
  #pragma unroll
  for (int rr=0;rr<2;rr++){
    int d = tid + rr*256;
    float4 v0, v1;
    v0.x=us[0][d]; v0.y=us[1][d]; v0.z=us[2][d]; v0.w=us[3][d];
    v1.x=us[4][d]; v1.y=us[5][d]; v1.z=us[6][d]; v1.w=us[7][d];
    float* dp = g_dtt + ((size_t)(b*DI + d))*LL + l0;
    *(float4*)dp = v0; *(float4*)(dp+4) = v1;
  }
}

// ---------------- SSM chunked parallel scan ----------------
__global__ void ssm_scan(const float* __restrict__ Alog, const float* __restrict__ Dp){
  __shared__ float sA[16][17], sB[16][17], sH[16][17];
  __shared__ float sv[256][17];
  const int bd = blockIdx.x;
  const int b = bd >> 9, d = bd & 511;
  const int tid = threadIdx.x;
  const int c = tid >> 4, s = tid & 15;
  const float As = -__expf(Alog[d*16 + s]);
  const float* dtp = g_dtt + ((size_t)(b*DI + d))*LL + c*16;
  const float* up  = g_ut  + ((size_t)(b*DI + d))*LL + c*16;
  const float* bcp = g_bc + ((size_t)(b*LL + c*16))*32 + s;
  float a[16], bv[16];
  #pragma unroll
  for (int i=0;i<16;i++){
    float dt = dtp[i], u = up[i];
    float Bm = bcp[i*32];
    a[i]  = __expf(dt * As);
    bv[i] = dt * u * Bm;
  }
  float Ap = 1.f, Bf = 0.f;
  #pragma unroll
  for (int i=0;i<16;i++){ Bf = fmaf(a[i], Bf, bv[i]); Ap *= a[i]; }
  sA[c][s] = Ap; sB[c][s] = Bf;
  __syncthreads();
  if (tid < 16){
    float h = 0.f;
    #pragma unroll
    for (int cc=0;cc<16;cc++){
      sH[cc][tid] = h;
      h = fmaf(sA[cc][tid], h, sB[cc][tid]);
    }
  }
  __syncthreads();
  float h = sH[c][s];
  #pragma unroll
  for (int i=0;i<16;i++){
    h = fmaf(a[i], h, bv[i]);
    float Cm = bcp[i*32 + 16];
    sv[c*16 + i][s] = h * Cm;
  }
  __syncthreads();
  float y = 0.f;
  #pragma unroll
  for (int ss=0;ss<16;ss++) y += sv[tid][ss];
  float u_t = g_ut[((size_t)(b*DI + d))*LL + tid];
  float zs  = g_zs[((size_t)(b*DI + d))*LL + tid];
  g_yt[((size_t)(b*DI + d))*LL + tid] = (y + u_t * Dp[d]) * zs;
}

// ---------------- decoder final layer: NHWC [b][16384][32] -> out [b][256][256] ----------------
__global__ void dec_last_kernel(const float* __restrict__ xn, const float* __restrict__ w4,
                                const float* __restrict__ b4, float* __restrict__ out){
  int idx = blockIdx.x*blockDim.x + threadIdx.x;   // BB*128*128
  int w_ = idx & 127; int t1 = idx >> 7; int h_ = t1 & 127; int b = t1 >> 7;
  const float* xp = xn + (size_t)idx*32;
  float bv = b4[0];
  float a0=bv, a1=bv, a2=bv, a3=bv;
  #pragma unroll
  for (int c4=0;c4<8;c4++){
    float4 xq = *(const float4*)(xp + c4*4);
    #pragma unroll
    for (int j=0;j<4;j++){
      float xv = (&xq.x)[j];
      float4 wt = *(const float4*)(w4 + (c4*4+j)*4);
      a0=fmaf(xv,wt.x,a0); a1=fmaf(xv,wt.y,a1); a2=fmaf(xv,wt.z,a2); a3=fmaf(xv,wt.w,a3);
    }
  }
  float* op = out + (((size_t)b*256 + 2*h_)*256 + 2*w_);
  *(float2*)op         = make_float2(a0,a1);
  *(float2*)(op + 256) = make_float2(a2,a3);
}

// ---------------- launch ----------------
extern "C" void kernel_launch(void* const* d_in, const int* in_sizes, int n_in,
                              void* d_out, int out_size){
  const float* x       = (const float*)d_in[0];
  const int*   t       = (const int*)d_in[1];
  const float* time_w1 = (const float*)d_in[2];
  const float* time_b1 = (const float*)d_in[3];
  const float* time_w2 = (const float*)d_in[4];
  const float* time_b2 = (const float*)d_in[5];
  const float* patch_w = (const float*)d_in[6];
  const float* patch_b = (const float*)d_in[7];
  const float* pos     = (const float*)d_in[8];
  const float* ln_g    = (const float*)d_in[9];
  const float* ln_b    = (const float*)d_in[10];
  const float* in_proj = (const float*)d_in[11];
  const float* conv_w  = (const float*)d_in[12];
  const float* conv_b  = (const float*)d_in[13];
  const float* x_proj  = (const float*)d_in[14];
  const float* dt_w    = (const float*)d_in[15];
  const float* dt_b    = (const float*)d_in[16];
  const float* A_log   = (const float*)d_in[17];
  const float* Dp      = (const float*)d_in[18];
  const float* out_proj= (const float*)d_in[19];
  const float* dw1 = (const float*)d_in[20];
  const float* db1 = (const float*)d_in[21];
  const float* dw2 = (const float*)d_in[22];
  const float* db2 = (const float*)d_in[23];
  const float* dw3 = (const float*)d_in[24];
  const float* db3 = (const float*)d_in[25];
  const float* dw4 = (const float*)d_in[26];
  const float* db4 = (const float*)d_in[27];

  float *p_patches,*p_h,*p_xz,*p_temb,*p_yt,*p_d1,*p_d2,*p_d3;
  unsigned *p_wpi,*p_wpo,*p_wpp,*p_wd1,*p_wd2,*p_wd3;
  cudaGetSymbolAddress((void**)&p_patches, g_patches);
  cudaGetSymbolAddress((void**)&p_h, g_h);
  cudaGetSymbolAddress((void**)&p_xz, g_xz);
  cudaGetSymbolAddress((void**)&p_temb, g_temb);
  cudaGetSymbolAddress((void**)&p_yt, g_yt);
  cudaGetSymbolAddress((void**)&p_d1, g_d1);
  cudaGetSymbolAddress((void**)&p_d2, g_d2);
  cudaGetSymbolAddress((void**)&p_d3, g_d3);
  cudaGetSymbolAddress((void**)&p_wpi, g_wp_in);
  cudaGetSymbolAddress((void**)&p_wpo, g_wp_out);
  cudaGetSymbolAddress((void**)&p_wpp, g_wp_patch);
  cudaGetSymbolAddress((void**)&p_wd1, g_wp_d1);
  cudaGetSymbolAddress((void**)&p_wd2, g_wp_d2);
  cudaGetSymbolAddress((void**)&p_wd3, g_wp_d3);

  cudaFuncSetAttribute(mma_gemm<1,0,1>, cudaFuncAttributeMaxDynamicSharedMemorySize, SMEM_BM64);
  cudaFuncSetAttribute(mma_gemm<2,1,0>, cudaFuncAttributeMaxDynamicSharedMemorySize, SMEM_BM128);
  cudaFuncSetAttribute(mma_gemm<1,2,2>, cudaFuncAttributeMaxDynamicSharedMemorySize, SMEM_BM64);
  cudaFuncSetAttribute(mma_gemm<1,0,3>, cudaFuncAttributeMaxDynamicSharedMemorySize, SMEM_BM64);

  // ordered so the 4th launch (ncu capture) is patch_gemm
  patch_gather_kernel<<<(NTOK*512)/256, 256>>>(x);
  time_emb_kernel<<<dim3(BB,8), 256>>>(t, time_w1, time_b1, time_w2, time_b2);
  wpack_kernel<<<(EE*512/2 + 255)/256, 256>>>(patch_w, p_wpp, EE*512/2);
  mma_gemm<1,0,1><<<dim3(EE/64, NTOK/64), 256, SMEM_BM64>>>(
      p_patches, p_wpp, nullptr, nullptr, patch_b, pos, p_temb, p_h, 512, EE);

  wpack_kernel<<<(DEPTH*XZW*EE/2 + 255)/256, 256>>>(in_proj, p_wpi, DEPTH*XZW*EE/2);
  wpack_kernel<<<(DEPTH*EE*DI/2 + 255)/256, 256>>>(out_proj, p_wpo, DEPTH*EE*DI/2);
  wpack_t_kernel<<<(512*128 + 255)/256, 256>>>(dw1, p_wd1, 512, 256);
  wpack_t_kernel<<<(256*64 + 255)/256, 256>>>(dw2, p_wd2, 256, 128);
  wpack_t_kernel<<<(128*32 + 255)/256, 256>>>(dw3, p_wd3, 128, 64);

  for (int i=0;i<DEPTH;i++){
    mma_gemm<2,1,0><<<dim3(XZW/64, NTOK/128), 256, SMEM_BM128>>>(
        p_h, p_wpi + (size_t)i*XZW*EE,
        ln_g + (size_t)i*EE, ln_b + (size_t)i*EE,
        nullptr, nullptr, nullptr, p_xz, EE, XZW);
    prep_kernel<<<NTOK/8, 256>>>(conv_w + (size_t)i*DI*DCN, conv_b + (size_t)i*DI,
                                 x_proj + (size_t)i*48*DI,
                                 dt_w + (size_t)i*DI*DTRN, dt_b + (size_t)i*DI);
    ssm_scan<<<BB*DI, 256>>>(A_log + (size_t)i*DI*DS, Dp + (size_t)i*DI);
    mma_gemm<1,2,2><<<dim3(EE/64, NTOK/64), 256, SMEM_BM64>>>(
        p_yt, p_wpo + (size_t)i*EE*DI,
        nullptr, nullptr, nullptr, nullptr, nullptr, p_h, DI, EE);
  }

  // decoder as convT GEMMs, NHWC chain
  mma_gemm<1,0,3><<<dim3(512/64, 2048/64), 256, SMEM_BM64>>>(
      p_h, p_wd1, nullptr, nullptr, db1, nullptr, nullptr, p_d1, 256, 512, 8, 4);
  mma_gemm<1,0,3><<<dim3(256/64, 8192/64), 256, SMEM_BM64>>>(
      p_d1, p_wd2, nullptr, nullptr, db2, nullptr, nullptr, p_d2, 128, 256, 10, 5);
  mma_gemm<1,0,3><<<dim3(128/64, 32768/64), 256, SMEM_BM64>>>(
      p_d2, p_wd3, nullptr, nullptr, db3, nullptr, nullptr, p_d3, 64, 128, 12, 6);
  dec_last_kernel<<<(BB*128*128)/256, 256>>>(p_d3, dw4, db4, (float*)d_out);
}

// round 17
// speedup vs baseline: 1.2005x; 1.0204x over previous
#include <cuda_runtime.h>
#include <cuda_bf16.h>
#include <math.h>

#define BB 8
#define IMG 256
#define INCH 2
#define PSZ 16
#define EE 256
#define DEPTH 8
#define HPN 16
#define LL 256
#define DI 512
#define DS 16
#define DTRN 16
#define DCN 4
#define NTOK 2048          // B*L
#define XZW 1024           // 2*DI

// ---------------- scratch ----------------
__device__ float g_temb[BB*EE];
__device__ float g_h[NTOK*EE];
__device__ float g_patches[NTOK*512];
__device__ float g_xz[NTOK*XZW];
__device__ float g_ut[BB*DI*LL];
__device__ float g_dtt[BB*DI*LL];
__device__ float g_zs[BB*DI*LL];
__device__ float g_bc[NTOK*32];
__device__ float g_yt[BB*DI*LL];
__device__ float g_d1[BB*128*32*32];   // NHWC [b][1024][128]
__device__ float g_d2[BB*64*64*64];    // NHWC [b][4096][64]
__device__ float g_d3[BB*32*128*128];  // NHWC [b][16384][32]
__device__ unsigned g_wp_in[DEPTH*XZW*EE];
__device__ unsigned g_wp_out[DEPTH*EE*DI];
__device__ unsigned g_wp_patch[EE*512];
__device__ unsigned g_wp_d1[512*256];
__device__ unsigned g_wp_d2[256*128];
__device__ unsigned g_wp_d3[128*64];

__device__ __forceinline__ float geluf(float v){ return 0.5f*v*(1.0f+erff(v*0.70710678118654752f)); }
__device__ __forceinline__ float siluf(float v){ return v/(1.0f+__expf(-v)); }

__device__ __forceinline__ void mma16(float* d, const unsigned* a, unsigned b0, unsigned b1){
  asm volatile("mma.sync.aligned.m16n8k16.row.col.f32.bf16.bf16.f32 "
    "{%0,%1,%2,%3}, {%4,%5,%6,%7}, {%8,%9}, {%0,%1,%2,%3};"
    : "+f"(d[0]),"+f"(d[1]),"+f"(d[2]),"+f"(d[3])
    : "r"(a[0]),"r"(a[1]),"r"(a[2]),"r"(a[3]), "r"(b0),"r"(b1));
}
__device__ __forceinline__ void cpasync16(unsigned saddr, const void* g){
  asm volatile("cp.async.cg.shared.global [%0], [%1], 16;" :: "r"(saddr), "l"(g));
}
#define CP_COMMIT() asm volatile("cp.async.commit_group;" ::: "memory")
#define CP_WAIT0()  asm volatile("cp.async.wait_group 0;" ::: "memory")

__device__ __forceinline__ void store_split(unsigned* base, int widx, float4 v){
  __nv_bfloat162 h0 = __floats2bfloat162_rn(v.x, v.y);
  __nv_bfloat162 h1 = __floats2bfloat162_rn(v.z, v.w);
  float r0 = v.x - __bfloat162float(h0.x);
  float r1 = v.y - __bfloat162float(h0.y);
  float r2 = v.z - __bfloat162float(h1.x);
  float r3 = v.w - __bfloat162float(h1.y);
  __nv_bfloat162 l0 = __floats2bfloat162_rn(r0, r1);
  __nv_bfloat162 l1 = __floats2bfloat162_rn(r2, r3);
  uint4 w;
  w.x = *(unsigned*)&h0; w.y = *(unsigned*)&l0;
  w.z = *(unsigned*)&h1; w.w = *(unsigned*)&l1;
  *(uint4*)(base + widx) = w;
}
__device__ __forceinline__ void store_split2(unsigned* base, int widx, float a0, float a1){
  __nv_bfloat162 h = __floats2bfloat162_rn(a0, a1);
  float r0 = a0 - __bfloat162float(h.x);
  float r1 = a1 - __bfloat162float(h.y);
  __nv_bfloat162 l = __floats2bfloat162_rn(r0, r1);
  uint2 w; w.x = *(unsigned*)&h; w.y = *(unsigned*)&l;
  *(uint2*)(base + widx) = w;
}
__device__ __forceinline__ uint2 pack_pair(float a0, float a1){
  __nv_bfloat162 h = __floats2bfloat162_rn(a0, a1);
  float r0 = a0 - __bfloat162float(h.x);
  float r1 = a1 - __bfloat162float(h.y);
  __nv_bfloat162 l = __floats2bfloat162_rn(r0, r1);
  uint2 w; w.x = *(unsigned*)&h; w.y = *(unsigned*)&l;
  return w;
}

// ---------------- weight pre-pack ----------------
__global__ void wpack_kernel(const float* __restrict__ W, unsigned* __restrict__ P, int total_pairs){
  int idx = blockIdx.x*blockDim.x + threadIdx.x;
  if (idx >= total_pairs) return;
  float2 v = *(const float2*)(W + (size_t)idx*2);
  *(uint2*)(P + (size_t)idx*2) = pack_pair(v.x, v.y);
}
__global__ void wpack_t_kernel(const float* __restrict__ W, unsigned* __restrict__ P, int N, int K){
  int idx = blockIdx.x*blockDim.x + threadIdx.x;
  int total = N*(K/2);
  if (idx >= total) return;
  int n = idx / (K/2), kp = idx % (K/2);
  float a0 = W[(size_t)(2*kp)*N + n];
  float a1 = W[(size_t)(2*kp+1)*N + n];
  *(uint2*)(P + (size_t)n*K + 2*kp) = pack_pair(a0, a1);
}

// ---------------- time embedding ----------------
__global__ void time_emb_kernel(const int* __restrict__ t, const float* __restrict__ w1,
                                const float* __restrict__ b1, const float* __restrict__ w2,
                                const float* __restrict__ b2){
  __shared__ float hdn[EE];
  __shared__ float part[8][33];
  int b = blockIdx.x, jg = blockIdx.y;
  int tid = threadIdx.x;
  float tf = (float)t[b];
  hdn[tid] = geluf(tf*w1[tid] + b1[tid]);
  __syncthreads();
  int j = jg*32 + (tid & 31);
  int kg = tid >> 5;
  float acc = 0.f;
  #pragma unroll 8
  for (int k = kg*32; k < kg*32+32; k++) acc = fmaf(hdn[k], w2[k*EE + j], acc);
  part[kg][tid & 31] = acc;
  __syncthreads();
  if (tid < 32){
    int jj = jg*32 + tid;
    float s = b2[jj];
    #pragma unroll
    for (int i=0;i<8;i++) s += part[i][tid];
    g_temb[b*EE + jj] = s;
  }
}

// ---------------- im2col patch gather ----------------
__global__ void patch_gather_kernel(const float* __restrict__ x){
  int idx = blockIdx.x*blockDim.x + threadIdx.x;
  int k = idx & 511; int tok = idx >> 9;
  int l = tok & (LL-1); int b = tok >> 8;
  int c = k >> 8; int rem = k & 255; int p = rem >> 4; int q = rem & 15;
  int hp = l >> 4; int wp = l & 15;
  g_patches[idx] = x[(((size_t)(b*INCH + c))*IMG + hp*PSZ + p)*IMG + wp*PSZ + q];
}

// ================= generic bf16x3 GEMM (BM 64/128 x BN 64) =================
#define B_SZI (64*40)
#define SMEM_BM64  ((2*64*40 + 2*B_SZI)*4)
#define SMEM_BM128 ((2*128*40 + 2*B_SZI)*4 + 256*4)
template<int MTILES,int ASRC,int EPI>
__global__ void __launch_bounds__(256)
mma_gemm(const float* __restrict__ A, const unsigned* __restrict__ Wp,
         const float* __restrict__ lng, const float* __restrict__ lnb,
         const float* __restrict__ bias, const float* __restrict__ pos,
         const float* __restrict__ temb, float* __restrict__ C,
         int K, int N, int lgRPB = 0, int lgW = 0)
{
  constexpr int BM = 64*MTILES;
  constexpr int A_SZI = BM*40;
  extern __shared__ unsigned smem_u[];
  unsigned* uA = smem_u;
  unsigned* uB = smem_u + 2*A_SZI;
  float* s_mu = (float*)(smem_u + 2*A_SZI + 2*B_SZI);
  float* s_rs = s_mu + 128;

  const int tid = threadIdx.x;
  const int m0 = blockIdx.y*BM, n0 = blockIdx.x*64;

  if (ASRC==1){
    int r = tid>>1, hf = tid&1;
    const float4* row = (const float4*)(A + (size_t)(m0+r)*K + hf*(K/2));
    float s=0.f, sq=0.f;
    for (int i=0;i<K/8;i++){ float4 v=row[i];
      s += v.x+v.y+v.z+v.w; sq += v.x*v.x+v.y*v.y+v.z*v.z+v.w*v.w; }
    s  += __shfl_xor_sync(0xffffffffu, s, 1);
    sq += __shfl_xor_sync(0xffffffffu, sq, 1);
    if (!hf){
      float muv = s/(float)K;
      float var = sq/(float)K - muv*muv;
      s_mu[r]=muv; s_rs[r]=rsqrtf(var+1e-5f);
    }
    __syncthreads();
  }

  const int amr = tid>>3;
  const int akc = (tid&7)*4;
  const int aq4 = (tid>>4)*4;
  const int apd = (tid&15)*2;
  const int NK = K/32;
  const float* Ak = (ASRC==2) ? (A + (size_t)(m0>>8)*DI*LL + (m0&255)) : A;

  {
    if (ASRC==2){
      float4 v0 = *(const float4*)(Ak + (size_t)apd*LL + aq4);
      float4 v1 = *(const float4*)(Ak + (size_t)(apd+1)*LL + aq4);
      #pragma unroll
      for (int j=0;j<4;j++)
        store_split2(uA, (aq4+j)*40 + apd, (&v0.x)[j], (&v1.x)[j]);
    } else {
      float4 g4, b4;
      if (ASRC==1){ g4 = *(const float4*)(lng+akc); b4 = *(const float4*)(lnb+akc); }
      #pragma unroll
      for (int i=0;i<BM/32;i++){
        int m = amr + i*32;
        float4 v = *(const float4*)(A + (size_t)(m0+m)*K + akc);
        if (ASRC==1){
          float mu = s_mu[m], rs = s_rs[m];
          v.x=(v.x-mu)*rs*g4.x+b4.x; v.y=(v.y-mu)*rs*g4.y+b4.y;
          v.z=(v.z-mu)*rs*g4.z+b4.z; v.w=(v.w-mu)*rs*g4.w+b4.w;
        }
        store_split(uA, m*40 + akc, v);
      }
    }
    #pragma unroll
    for (int i=0;i<2;i++){
      int p = tid + i*256;
      int n = p>>3, kc4 = (p&7)*4;
      uint4 v = *(const uint4*)(Wp + (size_t)(n0+n)*K + kc4);
      *(uint4*)(uB + n*40 + kc4) = v;
    }
  }
  __syncthreads();

  const int lane = tid&31, wid = tid>>5;
  const int wm = (wid>>1)*(16*MTILES), wn = (wid&1)*32;
  const int g = lane>>2, tg = lane&3;
  float acc[MTILES][4][4] = {};

  float4 pa[ASRC==2?2:(BM/32)], pg4, pb4;
  uint4 pbu[2];
  for (int ks=0; ks<NK; ks++){
    const int buf = ks&1;
    if (ks+1 < NK){
      int k0 = (ks+1)*32;
      if (ASRC==2){
        pa[0] = *(const float4*)(Ak + (size_t)(k0+apd)*LL + aq4);
        pa[1] = *(const float4*)(Ak + (size_t)(k0+apd+1)*LL + aq4);
      } else {
        if (ASRC==1){ pg4 = *(const float4*)(lng+k0+akc); pb4 = *(const float4*)(lnb+k0+akc); }
        #pragma unroll
        for (int i=0;i<(ASRC==2?0:BM/32);i++)
          pa[i] = *(const float4*)(A + (size_t)(m0+amr+i*32)*K + k0 + akc);
      }
      #pragma unroll
      for (int i=0;i<2;i++){
        int p = tid + i*256;
        pbu[i] = *(const uint4*)(Wp + (size_t)(n0+(p>>3))*K + k0 + (p&7)*4);
      }
    }
    const unsigned* As_ = uA + buf*A_SZI;
    const unsigned* Bs_ = uB + buf*B_SZI;
    #pragma unroll
    for (int h=0; h<2; h++){
      const int kb = h*8;
      unsigned bh[4][2], bl[4][2];
      #pragma unroll
      for (int nt=0;nt<4;nt++){
        int nb = wn + nt*8 + g;
        uint2 p0 = *(const uint2*)&Bs_[nb*40 + (kb+tg)*2];
        uint2 p1 = *(const uint2*)&Bs_[nb*40 + (kb+tg+4)*2];
        bh[nt][0]=p0.x; bl[nt][0]=p0.y;
        bh[nt][1]=p1.x; bl[nt][1]=p1.y;
      }
      #pragma unroll
      for (int mt=0;mt<MTILES;mt++){
        int mb = wm + mt*16;
        uint2 q00 = *(const uint2*)&As_[(mb+g  )*40 + (kb+tg)*2];
        uint2 q10 = *(const uint2*)&As_[(mb+g+8)*40 + (kb+tg)*2];
        uint2 q01 = *(const uint2*)&As_[(mb+g  )*40 + (kb+tg+4)*2];
        uint2 q11 = *(const uint2*)&As_[(mb+g+8)*40 + (kb+tg+4)*2];
        unsigned ah[4] = {q00.x, q10.x, q01.x, q11.x};
        unsigned al[4] = {q00.y, q10.y, q01.y, q11.y};
        #pragma unroll
        for (int nt=0;nt<4;nt++){
          mma16(acc[mt][nt], ah, bh[nt][0], bh[nt][1]);
          mma16(acc[mt][nt], al, bh[nt][0], bh[nt][1]);
          mma16(acc[mt][nt], ah, bl[nt][0], bl[nt][1]);
        }
      }
    }
    if (ks+1 < NK){
      unsigned* dA = uA + (buf^1)*A_SZI;
      unsigned* dB = uB + (buf^1)*B_SZI;
      if (ASRC==2){
        #pragma unroll
        for (int j=0;j<4;j++)
          store_split2(dA, (aq4+j)*40 + apd, (&pa[0].x)[j], (&pa[1].x)[j]);
      } else {
        #pragma unroll
        for (int i=0;i<(ASRC==2?0:BM/32);i++){
          int m = amr + i*32;
          float4 v = pa[i];
          if (ASRC==1){
            float mu = s_mu[m], rs = s_rs[m];
            v.x=(v.x-mu)*rs*pg4.x+pb4.x; v.y=(v.y-mu)*rs*pg4.y+pb4.y;
            v.z=(v.z-mu)*rs*pg4.z+pb4.z; v.w=(v.w-mu)*rs*pg4.w+pb4.w;
          }
          store_split(dA, m*40 + akc, v);
        }
      }
      #pragma unroll
      for (int i=0;i<2;i++){
        int p = tid + i*256;
        *(uint4*)(dB + (p>>3)*40 + (p&7)*4) = pbu[i];
      }
    }
    __syncthreads();
  }

  #pragma unroll
  for (int mt=0;mt<MTILES;mt++){
    #pragma unroll
    for (int nt=0;nt<4;nt++){
      int row = m0 + wm + mt*16 + g;
      int col = n0 + wn + nt*8 + tg*2;
      float2 v0 = make_float2(acc[mt][nt][0], acc[mt][nt][1]);
      float2 v1 = make_float2(acc[mt][nt][2], acc[mt][nt][3]);
      if (EPI==3){
        float vv[4] = {v0.x, v0.y, v1.x, v1.y};
        int rr[4] = {row, row, row+8, row+8};
        int cc[4] = {col, col+1, col, col+1};
        int O = N >> 2;
        int rpbm = (1<<lgRPB) - 1, wm_ = (1<<lgW) - 1;
        #pragma unroll
        for (int e=0;e<4;e++){
          int o = cc[e]>>2, p = (cc[e]>>1)&1, q = cc[e]&1;
          int bb_ = rr[e]>>lgRPB, hw = rr[e] & rpbm;
          int hh = hw>>lgW, ww = hw & wm_;
          size_t pix = ((size_t)bb_<<(lgRPB+2)) + (size_t)((2*hh+p)<<(lgW+1)) + (2*ww+q);
          C[pix*O + o] = geluf(vv[e] + bias[o]);
        }
      } else {
        if (EPI==1){
          int l0i = row & 255, b0i = row >> 8;
          int l1i = (row+8) & 255, b1i = (row+8) >> 8;
          v0.x += bias[col]   + pos[(size_t)l0i*EE+col]   + temb[(size_t)b0i*EE+col];
          v0.y += bias[col+1] + pos[(size_t)l0i*EE+col+1] + temb[(size_t)b0i*EE+col+1];
          v1.x += bias[col]   + pos[(size_t)l1i*EE+col]   + temb[(size_t)b1i*EE+col];
          v1.y += bias[col+1] + pos[(size_t)l1i*EE+col+1] + temb[(size_t)b1i*EE+col+1];
        } else if (EPI==2){
          float2 o0 = *(float2*)(C + (size_t)row*N + col);
          float2 o1 = *(float2*)(C + (size_t)(row+8)*N + col);
          v0.x += o0.x; v0.y += o0.y; v1.x += o1.x; v1.y += o1.y;
        }
        *(float2*)(C + (size_t)row*N + col) = v0;
        *(float2*)(C + (size_t)(row+8)*N + col) = v1;
      }
    }
  }
}

// ================= in_proj GEMM: BM128 x BN128, fused LN, cp.async B ==============
#define IP_ASZ (128*40)
#define IP_BSZ (128*40)
#define SMEM_IP ((2*IP_ASZ + 2*IP_BSZ)*4 + 256*4)
__global__ void __launch_bounds__(256)
inproj_gemm(const float* __restrict__ A, const unsigned* __restrict__ Wp,
            const float* __restrict__ lng, const float* __restrict__ lnb,
            float* __restrict__ C)
{
  const int K = EE, N = XZW;
  extern __shared__ unsigned smem_u[];
  unsigned* uA = smem_u;
  unsigned* uB = smem_u + 2*IP_ASZ;
  float* s_mu = (float*)(smem_u + 2*IP_ASZ + 2*IP_BSZ);
  float* s_rs = s_mu + 128;
  const unsigned uBaddr = (unsigned)__cvta_generic_to_shared(uB);

  const int tid = threadIdx.x;
  const int m0 = blockIdx.y*128, n0 = blockIdx.x*128;

  // LN row stats: each thread sums one half (K/2 = 128 floats = K/8 float4s)
  {
    int r = tid>>1, hf = tid&1;
    const float4* row = (const float4*)(A + (size_t)(m0+r)*K + hf*(K/2));
    float s=0.f, sq=0.f;
    #pragma unroll
    for (int i=0;i<K/8;i++){ float4 v=row[i];
      s += v.x+v.y+v.z+v.w; sq += v.x*v.x+v.y*v.y+v.z*v.z+v.w*v.w; }
    s  += __shfl_xor_sync(0xffffffffu, s, 1);
    sq += __shfl_xor_sync(0xffffffffu, sq, 1);
    if (!hf){
      float muv = s/(float)K;
      float var = sq/(float)K - muv*muv;
      s_mu[r]=muv; s_rs[r]=rsqrtf(var+1e-5f);
    }
    __syncthreads();
  }

  const int amr = tid>>3;            // A row base (0..31)
  const int akc = (tid&7)*4;         // k offset in chunk
  const int bn  = tid>>1;            // B row (0..127)
  const int bhw = (tid&1)*16;        // B word half
  const int NK = K/32;               // 8

  // chunk 0
  {
    const unsigned* src = Wp + (size_t)(n0+bn)*K + bhw;
    unsigned dst = uBaddr + (bn*40 + bhw)*4;
    #pragma unroll
    for (int i=0;i<4;i++) cpasync16(dst + i*16, src + i*4);
    CP_COMMIT();
    float4 g4 = *(const float4*)(lng+akc);
    float4 b4 = *(const float4*)(lnb+akc);
    #pragma unroll
    for (int i=0;i<4;i++){
      int m = amr + i*32;
      float4 v = *(const float4*)(A + (size_t)(m0+m)*K + akc);
      float mu = s_mu[m], rs = s_rs[m];
      v.x=(v.x-mu)*rs*g4.x+b4.x; v.y=(v.y-mu)*rs*g4.y+b4.y;
      v.z=(v.z-mu)*rs*g4.z+b4.z; v.w=(v.w-mu)*rs*g4.w+b4.w;
      store_split(uA, m*40 + akc, v);
    }
    CP_WAIT0();
  }
  __syncthreads();

  const int lane = tid&31, wid = tid>>5;
  const int wm = (wid>>2)*64, wn = (wid&3)*32;
  const int g = lane>>2, tg = lane&3;
  float acc[4][4][4] = {};

  float4 pa[4], pg4, pb4;
  for (int ks=0; ks<NK; ks++){
    const int buf = ks&1;
    if (ks+1 < NK){
      int k0 = (ks+1)*32;
      const unsigned* src = Wp + (size_t)(n0+bn)*K + k0 + bhw;
      unsigned dst = uBaddr + ((buf^1)*IP_BSZ + bn*40 + bhw)*4;
      #pragma unroll
      for (int i=0;i<4;i++) cpasync16(dst + i*16, src + i*4);
      CP_COMMIT();
      pg4 = *(const float4*)(lng+k0+akc); pb4 = *(const float4*)(lnb+k0+akc);
      #pragma unroll
      for (int i=0;i<4;i++)
        pa[i] = *(const float4*)(A + (size_t)(m0+amr+i*32)*K + k0 + akc);
    }
    const unsigned* As_ = uA + buf*IP_ASZ;
    const unsigned* Bs_ = uB + buf*IP_BSZ;
    #pragma unroll
    for (int h=0; h<2; h++){
      const int kb = h*8;
      unsigned bh[4][2], bl[4][2];
      #pragma unroll
      for (int nt=0;nt<4;nt++){
        int nb = wn + nt*8 + g;
        uint2 p0 = *(const uint2*)&Bs_[nb*40 + (kb+tg)*2];
        uint2 p1 = *(const uint2*)&Bs_[nb*40 + (kb+tg+4)*2];
        bh[nt][0]=p0.x; bl[nt][0]=p0.y;
        bh[nt][1]=p1.x; bl[nt][1]=p1.y;
      }
      #pragma unroll
      for (int mt=0;mt<4;mt++){
        int mb = wm + mt*16;
        uint2 q00 = *(const uint2*)&As_[(mb+g  )*40 + (kb+tg)*2];
        uint2 q10 = *(const uint2*)&As_[(mb+g+8)*40 + (kb+tg)*2];
        uint2 q01 = *(const uint2*)&As_[(mb+g  )*40 + (kb+tg+4)*2];
        uint2 q11 = *(const uint2*)&As_[(mb+g+8)*40 + (kb+tg+4)*2];
        unsigned ah[4] = {q00.x, q10.x, q01.x, q11.x};
        unsigned al[4] = {q00.y, q10.y, q01.y, q11.y};
        #pragma unroll
        for (int nt=0;nt<4;nt++){
          mma16(acc[mt][nt], ah, bh[nt][0], bh[nt][1]);
          mma16(acc[mt][nt], al, bh[nt][0], bh[nt][1]);
          mma16(acc[mt][nt], ah, bl[nt][0], bl[nt][1]);
        }
      }
    }
    if (ks+1 < NK){
      unsigned* dA = uA + (buf^1)*IP_ASZ;
      #pragma unroll
      for (int i=0;i<4;i++){
        int m = amr + i*32;
        float4 v = pa[i];
        float mu = s_mu[m], rs = s_rs[m];
        v.x=(v.x-mu)*rs*pg4.x+pb4.x; v.y=(v.y-mu)*rs*pg4.y+pb4.y;
        v.z=(v.z-mu)*rs*pg4.z+pb4.z; v.w=(v.w-mu)*rs*pg4.w+pb4.w;
        store_split(dA, m*40 + akc, v);
      }
      CP_WAIT0();
    }
    __syncthreads();
  }

  #pragma unroll
  for (int mt=0;mt<4;mt++){
    #pragma unroll
    for (int nt=0;nt<4;nt++){
      int row = m0 + wm + mt*16 + g;
      int col = n0 + wn + nt*8 + tg*2;
      *(float2*)(C + (size_t)row*N + col)     = make_float2(acc[mt][nt][0], acc[mt][nt][1]);
      *(float2*)(C + (size_t)(row+8)*N + col) = make_float2(acc[mt][nt][2], acc[mt][nt][3]);
    }
  }
}

// ---------------- fused prep ----------------
__global__ void prep_kernel(const float* __restrict__ cw, const float* __restrict__ cb,
                            const float* __restrict__ xw,
                            const float* __restrict__ dtw,
                            const float* __restrict__ dtb){
  __shared__ float us[8][513];
  __shared__ float pool[48*129];
  __shared__ float dbc_s[8][52];
  const int tid = threadIdx.x;
  const int b  = blockIdx.x >> 5;
  const int l0 = (blockIdx.x & 31) * 8;
  float* zsm = pool;
  #pragma unroll
  for (int r=0;r<16;r++){
    int idx = r*256 + tid;
    int d  = idx & 511;
    int ti = idx >> 9;
    int l  = l0 + ti;
    float acc = cb[d];
    #pragma unroll
    for (int j=0;j<4;j++){
      int ls = l + j - 3;
      if (ls >= 0) acc = fmaf(g_xz[((size_t)(b*LL + ls))*XZW + d], cw[d*4 + j], acc);
    }
    us[ti][d] = siluf(acc);
    float z = g_xz[((size_t)(b*LL + l))*XZW + DI + d];
    zsm[ti*516 + d] = siluf(z);
  }
  __syncthreads();
  #pragma unroll
  for (int rr=0;rr<2;rr++){
    int d = tid + rr*256;
    float4 v0, v1, w0, w1;
    v0.x=us[0][d]; v0.y=us[1][d]; v0.z=us[2][d]; v0.w=us[3][d];
    v1.x=us[4][d]; v1.y=us[5][d]; v1.z=us[6][d]; v1.w=us[7][d];
    w0.x=zsm[0*516+d]; w0.y=zsm[1*516+d]; w0.z=zsm[2*516+d]; w0.w=zsm[3*516+d];
    w1.x=zsm[4*516+d]; w1.y=zsm[5*516+d]; w1.z=zsm[6*516+d]; w1.w=zsm[7*516+d];
    float* up = g_ut + ((size_t)(b*DI + d))*LL + l0;
    *(float4*)up = v0; *(float4*)(up+4) = v1;
    float* zp = g_zs + ((size_t)(b*DI + d))*LL + l0;
    *(float4*)zp = w0; *(float4*)(zp+4) = w1;
  }
  const int ti = tid >> 5, lane = tid & 31;
  float accA = 0.f, accB = 0.f;
  for (int kt=0;kt<4;kt++){
    __syncthreads();
    #pragma unroll
    for (int i=0;i<6;i++){
      int f = (tid + i*256)*4;
      int j = f >> 7, c = f & 127;
      float4 v = *(const float4*)(xw + (size_t)j*DI + kt*128 + c);
      pool[j*129+c]=v.x; pool[j*129+c+1]=v.y; pool[j*129+c+2]=v.z; pool[j*129+c+3]=v.w;
    }
    __syncthreads();
    #pragma unroll 4
    for (int c=0;c<128;c++){
      float a = us[ti][kt*128 + c];
      accA = fmaf(a, pool[lane*129 + c], accA);
      if (lane < 16) accB = fmaf(a, pool[(32+lane)*129 + c], accB);
    }
  }
  __syncthreads();
  dbc_s[ti][lane] = accA;
  if (lane < 16) dbc_s[ti][32 + lane] = accB;
  __syncthreads();
  {
    int tti = tid >> 5, jj = tid & 31;
    g_bc[((size_t)(b*LL) + l0 + tti)*32 + jj] = dbc_s[tti][16 + jj];
  }
  #pragma unroll
  for (int r=0;r<16;r++){
    int idx = r*256 + tid;
    int d  = idx & 511;
    int ti2 = idx >> 9;
    const float* dbp = dbc_s[ti2];
    const float4* dw4 = (const float4*)(dtw + (size_t)d*16);
    float4 w0 = dw4[0], w1 = dw4[1], w2 = dw4[2], w3 = dw4[3];
    float acc = dtb[d];
    acc=fmaf(dbp[0],w0.x,acc);  acc=fmaf(dbp[1],w0.y,acc);  acc=fmaf(dbp[2],w0.z,acc);  acc=fmaf(dbp[3],w0.w,acc);
    acc=fmaf(dbp[4],w1.x,acc);  acc=fmaf(dbp[5],w1.y,acc);  acc=fmaf(dbp[6],w1.z,acc);  acc=fmaf(dbp[7],w1.w,acc);
    acc=fmaf(dbp[8],w2.x,acc);  acc=fmaf(dbp[9],w2.y,acc);  acc=fmaf(dbp[10],w2.z,acc); acc=fmaf(dbp[11],w2.w,acc);
    acc=fmaf(dbp[12],w3.x,acc); acc=fmaf(dbp[13],w3.y,acc); acc=fmaf(dbp[14],w3.z,acc); acc=fmaf(dbp[15],w3.w,acc);
    us[ti2][d] = (acc > 20.f) ? acc : log1pf(__expf(acc));
  }
  __syncthreads();
  #pragma unroll
  for (int rr=0;rr<2;rr++){
    int d = tid + rr*256;
    float4 v0, v1;
    v0.x=us[0][d]; v0.y=us[1][d]; v0.z=us[2][d]; v0.w=us[3][d];
    v1.x=us[4][d]; v1.y=us[5][d]; v1.z=us[6][d]; v1.w=us[7][d];
    float* dp = g_dtt + ((size_t)(b*DI + d))*LL + l0;
    *(float4*)dp = v0; *(float4*)(dp+4) = v1;
  }
}

// ---------------- SSM chunked parallel scan ----------------
__global__ void ssm_scan(const float* __restrict__ Alog, const float* __restrict__ Dp){
  __shared__ float sA[16][17], sB[16][17], sH[16][17];
  __shared__ float sv[256][17];
  const int bd = blockIdx.x;
  const int b = bd >> 9, d = bd & 511;
  const int tid = threadIdx.x;
  const int c = tid >> 4, s = tid & 15;
  const float As = -__expf(Alog[d*16 + s]);
  const float* dtp = g_dtt + ((size_t)(b*DI + d))*LL + c*16;
  const float* up  = g_ut  + ((size_t)(b*DI + d))*LL + c*16;
  const float* bcp = g_bc + ((size_t)(b*LL + c*16))*32 + s;
  float a[16], bv[16];
  #pragma unroll
  for (int i=0;i<16;i++){
    float dt = dtp[i], u = up[i];
    float Bm = bcp[i*32];
    a[i]  = __expf(dt * As);
    bv[i] = dt * u * Bm;
  }
  float Ap = 1.f, Bf = 0.f;
  #pragma unroll
  for (int i=0;i<16;i++){ Bf = fmaf(a[i], Bf, bv[i]); Ap *= a[i]; }
  sA[c][s] = Ap; sB[c][s] = Bf;
  __syncthreads();
  if (tid < 16){
    float h = 0.f;
    #pragma unroll
    for (int cc=0;cc<16;cc++){
      sH[cc][tid] = h;
      h = fmaf(sA[cc][tid], h, sB[cc][tid]);
    }
  }
  __syncthreads();
  float h = sH[c][s];
  #pragma unroll
  for (int i=0;i<16;i++){
    h = fmaf(a[i], h, bv[i]);
    float Cm = bcp[i*32 + 16];
    sv[c*16 + i][s] = h * Cm;
  }
  __syncthreads();
  float y = 0.f;
  #pragma unroll
  for (int ss=0;ss<16;ss++) y += sv[tid][ss];
  float u_t = g_ut[((size_t)(b*DI + d))*LL + tid];
  float zs  = g_zs[((size_t)(b*DI + d))*LL + tid];
  g_yt[((size_t)(b*DI + d))*LL + tid] = (y + u_t * Dp[d]) * zs;
}

// ---------------- decoder final layer ----------------
__global__ void dec_last_kernel(const float* __restrict__ xn, const float* __restrict__ w4,
                                const float* __restrict__ b4, float* __restrict__ out){
  int idx = blockIdx.x*blockDim.x + threadIdx.x;
  int w_ = idx & 127; int t1 = idx >> 7; int h_ = t1 & 127; int b = t1 >> 7;
  const float* xp = xn + (size_t)idx*32;
  float bv = b4[0];
  float a0=bv, a1=bv, a2=bv, a3=bv;
  #pragma unroll
  for (int c4=0;c4<8;c4++){
    float4 xq = *(const float4*)(xp + c4*4);
    #pragma unroll
    for (int j=0;j<4;j++){
      float xv = (&xq.x)[j];
      float4 wt = *(const float4*)(w4 + (c4*4+j)*4);
      a0=fmaf(xv,wt.x,a0); a1=fmaf(xv,wt.y,a1); a2=fmaf(xv,wt.z,a2); a3=fmaf(xv,wt.w,a3);
    }
  }
  float* op = out + (((size_t)b*256 + 2*h_)*256 + 2*w_);
  *(float2*)op         = make_float2(a0,a1);
  *(float2*)(op + 256) = make_float2(a2,a3);
}

// ---------------- launch ----------------
extern "C" void kernel_launch(void* const* d_in, const int* in_sizes, int n_in,
                              void* d_out, int out_size){
  const float* x       = (const float*)d_in[0];
  const int*   t       = (const int*)d_in[1];
  const float* time_w1 = (const float*)d_in[2];
  const float* time_b1 = (const float*)d_in[3];
  const float* time_w2 = (const float*)d_in[4];
  const float* time_b2 = (const float*)d_in[5];
  const float* patch_w = (const float*)d_in[6];
  const float* patch_b = (const float*)d_in[7];
  const float* pos     = (const float*)d_in[8];
  const float* ln_g    = (const float*)d_in[9];
  const float* ln_b    = (const float*)d_in[10];
  const float* in_proj = (const float*)d_in[11];
  const float* conv_w  = (const float*)d_in[12];
  const float* conv_b  = (const float*)d_in[13];
  const float* x_proj  = (const float*)d_in[14];
  const float* dt_w    = (const float*)d_in[15];
  const float* dt_b    = (const float*)d_in[16];
  const float* A_log   = (const float*)d_in[17];
  const float* Dp      = (const float*)d_in[18];
  const float* out_proj= (const float*)d_in[19];
  const float* dw1 = (const float*)d_in[20];
  const float* db1 = (const float*)d_in[21];
  const float* dw2 = (const float*)d_in[22];
  const float* db2 = (const float*)d_in[23];
  const float* dw3 = (const float*)d_in[24];
  const float* db3 = (const float*)d_in[25];
  const float* dw4 = (const float*)d_in[26];
  const float* db4 = (const float*)d_in[27];

  float *p_patches,*p_h,*p_xz,*p_temb,*p_yt,*p_d1,*p_d2,*p_d3;
  unsigned *p_wpi,*p_wpo,*p_wpp,*p_wd1,*p_wd2,*p_wd3;
  cudaGetSymbolAddress((void**)&p_patches, g_patches);
  cudaGetSymbolAddress((void**)&p_h, g_h);
  cudaGetSymbolAddress((void**)&p_xz, g_xz);
  cudaGetSymbolAddress((void**)&p_temb, g_temb);
  cudaGetSymbolAddress((void**)&p_yt, g_yt);
  cudaGetSymbolAddress((void**)&p_d1, g_d1);
  cudaGetSymbolAddress((void**)&p_d2, g_d2);
  cudaGetSymbolAddress((void**)&p_d3, g_d3);
  cudaGetSymbolAddress((void**)&p_wpi, g_wp_in);
  cudaGetSymbolAddress((void**)&p_wpo, g_wp_out);
  cudaGetSymbolAddress((void**)&p_wpp, g_wp_patch);
  cudaGetSymbolAddress((void**)&p_wd1, g_wp_d1);
  cudaGetSymbolAddress((void**)&p_wd2, g_wp_d2);
  cudaGetSymbolAddress((void**)&p_wd3, g_wp_d3);

  cudaFuncSetAttribute(mma_gemm<1,0,1>, cudaFuncAttributeMaxDynamicSharedMemorySize, SMEM_BM64);
  cudaFuncSetAttribute(inproj_gemm,     cudaFuncAttributeMaxDynamicSharedMemorySize, SMEM_IP);
  cudaFuncSetAttribute(mma_gemm<1,2,2>, cudaFuncAttributeMaxDynamicSharedMemorySize, SMEM_BM64);
  cudaFuncSetAttribute(mma_gemm<1,0,3>, cudaFuncAttributeMaxDynamicSharedMemorySize, SMEM_BM64);

  patch_gather_kernel<<<(NTOK*512)/256, 256>>>(x);
  time_emb_kernel<<<dim3(BB,8), 256>>>(t, time_w1, time_b1, time_w2, time_b2);
  wpack_kernel<<<(EE*512/2 + 255)/256, 256>>>(patch_w, p_wpp, EE*512/2);
  mma_gemm<1,0,1><<<dim3(EE/64, NTOK/64), 256, SMEM_BM64>>>(
      p_patches, p_wpp, nullptr, nullptr, patch_b, pos, p_temb, p_h, 512, EE);

  wpack_kernel<<<(DEPTH*XZW*EE/2 + 255)/256, 256>>>(in_proj, p_wpi, DEPTH*XZW*EE/2);
  wpack_kernel<<<(DEPTH*EE*DI/2 + 255)/256, 256>>>(out_proj, p_wpo, DEPTH*EE*DI/2);
  wpack_t_kernel<<<(512*128 + 255)/256, 256>>>(dw1, p_wd1, 512, 256);
  wpack_t_kernel<<<(256*64 + 255)/256, 256>>>(dw2, p_wd2, 256, 128);
  wpack_t_kernel<<<(128*32 + 255)/256, 256>>>(dw3, p_wd3, 128, 64);

  for (int i=0;i<DEPTH;i++){
    inproj_gemm<<<dim3(XZW/128, NTOK/128), 256, SMEM_IP>>>(
        p_h, p_wpi + (size_t)i*XZW*EE,
        ln_g + (size_t)i*EE, ln_b + (size_t)i*EE, p_xz);
    prep_kernel<<<NTOK/8, 256>>>(conv_w + (size_t)i*DI*DCN, conv_b + (size_t)i*DI,
                                 x_proj + (size_t)i*48*DI,
                                 dt_w + (size_t)i*DI*DTRN, dt_b + (size_t)i*DI);
    ssm_scan<<<BB*DI, 256>>>(A_log + (size_t)i*DI*DS, Dp + (size_t)i*DI);
    mma_gemm<1,2,2><<<dim3(EE/64, NTOK/64), 256, SMEM_BM64>>>(
        p_yt, p_wpo + (size_t)i*EE*DI,
        nullptr, nullptr, nullptr, nullptr, nullptr, p_h, DI, EE);
  }

  mma_gemm<1,0,3><<<dim3(512/64, 2048/64), 256, SMEM_BM64>>>(
      p_h, p_wd1, nullptr, nullptr, db1, nullptr, nullptr, p_d1, 256, 512, 8, 4);
  mma_gemm<1,0,3><<<dim3(256/64, 8192/64), 256, SMEM_BM64>>>(
      p_d1, p_wd2, nullptr, nullptr, db2, nullptr, nullptr, p_d2, 128, 256, 10, 5);
  mma_gemm<1,0,3><<<dim3(128/64, 32768/64), 256, SMEM_BM64>>>(
      p_d2, p_wd3, nullptr, nullptr, db3, nullptr, nullptr, p_d3, 64, 128, 12, 6);
  dec_last_kernel<<<(BB*128*128)/256, 256>>>(p_d3, dw4, db4, (float*)d_out);
}